// round 12
// baseline (speedup 1.0000x reference)
#include <cuda_runtime.h>
#include <cuda_bf16.h>
#include <cstdint>

#define NDIM 384
#define NN   (NDIM * NDIM)   // 147456
#define DDIM 128

// ---- scratch (device globals; no allocation allowed) ----
__device__ __nv_bfloat16 g_left [(size_t)DDIM * NN];   // [d][i*N+k] bf16
__device__ __nv_bfloat16 g_right[(size_t)DDIM * NN];   // [d][j*N+k] bf16
__device__ float         g_outgate[(size_t)NN * DDIM]; // [pos][h] fp32
__device__ __nv_bfloat16 g_accbf[(size_t)DDIM * NN];   // [d][i*N+j] bf16 (einsum out)
__device__ __nv_bfloat16 g_wsp[5 * 32768];             // pre-split weights, frag layout

__device__ __forceinline__ float sigf(float v) { return 1.f / (1.f + __expf(-v)); }

// ---- shared mma helpers ----
__device__ __forceinline__ void ldm4(uint32_t (&r)[4], uint32_t saddr) {
    asm volatile("ldmatrix.sync.aligned.m8n8.x4.shared.b16 {%0,%1,%2,%3}, [%4];"
        : "=r"(r[0]), "=r"(r[1]), "=r"(r[2]), "=r"(r[3]) : "r"(saddr));
}
__device__ __forceinline__ void mma16816(float (&d)[4], const uint32_t (&a)[4],
                                         uint32_t b0, uint32_t b1) {
    asm volatile("mma.sync.aligned.m16n8k16.row.col.f32.bf16.bf16.f32 "
        "{%0,%1,%2,%3}, {%4,%5,%6,%7}, {%8,%9}, {%0,%1,%2,%3};"
        : "+f"(d[0]), "+f"(d[1]), "+f"(d[2]), "+f"(d[3])
        : "r"(a[0]), "r"(a[1]), "r"(a[2]), "r"(a[3]), "r"(b0), "r"(b1));
}
__device__ __forceinline__ void cpa16(uint32_t dst, const void* src) {
    asm volatile("cp.async.cg.shared.global [%0], [%1], 16;" :: "r"(dst), "l"(src));
}
__device__ __forceinline__ void cpaCommit() { asm volatile("cp.async.commit_group;"); }

// 128-col swizzled offset (elements)
__device__ __forceinline__ uint32_t sw128(int row, int chunk) {
    return (uint32_t)(row * 128 + (((chunk & 7) ^ (row & 7)) << 3) + ((chunk & 8) << 3));
}

// 3-pass split gemm (bf16x3): one accumulator
__device__ __forceinline__ void gemm3(float acc[2][4][4], int m0w, int n0w, int lane,
                                      uint32_t bxh, uint32_t bxl,
                                      uint32_t bwh, uint32_t bwl) {
    #pragma unroll
    for (int mi = 0; mi < 2; mi++)
        #pragma unroll
        for (int ni = 0; ni < 4; ni++)
            #pragma unroll
            for (int e = 0; e < 4; e++) acc[mi][ni][e] = 0.f;

    const int aRow = ((lane & 8) ? 8 : 0) + (lane & 7);
    const int aChk = (lane >> 4);
    const int bRow = ((lane & 16) ? 8 : 0) + (lane & 7);
    const int bChk = (lane >> 3) & 1;

    #pragma unroll
    for (int ks = 0; ks < 8; ks++) {
        uint32_t ah[2][4], al[2][4], bh[2][4], bl[2][4];
        #pragma unroll
        for (int mi = 0; mi < 2; mi++) {
            uint32_t off = sw128(m0w + mi * 16 + aRow, ks * 2 + aChk) * 2;
            ldm4(ah[mi], bxh + off);
            ldm4(al[mi], bxl + off);
        }
        #pragma unroll
        for (int p = 0; p < 2; p++) {
            uint32_t off = sw128(n0w + p * 16 + bRow, ks * 2 + bChk) * 2;
            ldm4(bh[p], bwh + off);
            ldm4(bl[p], bwl + off);
        }
        #pragma unroll
        for (int mi = 0; mi < 2; mi++) {
            mma16816(acc[mi][0], ah[mi], bh[0][0], bh[0][1]);
            mma16816(acc[mi][1], ah[mi], bh[0][2], bh[0][3]);
            mma16816(acc[mi][2], ah[mi], bh[1][0], bh[1][1]);
            mma16816(acc[mi][3], ah[mi], bh[1][2], bh[1][3]);
            mma16816(acc[mi][0], ah[mi], bl[0][0], bl[0][1]);
            mma16816(acc[mi][1], ah[mi], bl[0][2], bl[0][3]);
            mma16816(acc[mi][2], ah[mi], bl[1][0], bl[1][1]);
            mma16816(acc[mi][3], ah[mi], bl[1][2], bl[1][3]);
            mma16816(acc[mi][0], al[mi], bh[0][0], bh[0][1]);
            mma16816(acc[mi][1], al[mi], bh[0][2], bh[0][3]);
            mma16816(acc[mi][2], al[mi], bh[1][0], bh[1][1]);
            mma16816(acc[mi][3], al[mi], bh[1][2], bh[1][3]);
        }
    }
}

// fused dual gemm: accV vs weight(bVh,bVl), accG vs weight(bGh,bGl),
// sharing the A-fragment loads. Per-accumulator FP order identical to gemm3.
__device__ __forceinline__ void gemm3x2(float accV[2][4][4], float accG[2][4][4],
                                        int m0w, int n0w, int lane,
                                        uint32_t bxh, uint32_t bxl,
                                        uint32_t bVh, uint32_t bVl,
                                        uint32_t bGh, uint32_t bGl) {
    #pragma unroll
    for (int mi = 0; mi < 2; mi++)
        #pragma unroll
        for (int ni = 0; ni < 4; ni++)
            #pragma unroll
            for (int e = 0; e < 4; e++) { accV[mi][ni][e] = 0.f; accG[mi][ni][e] = 0.f; }

    const int aRow = ((lane & 8) ? 8 : 0) + (lane & 7);
    const int aChk = (lane >> 4);
    const int bRow = ((lane & 16) ? 8 : 0) + (lane & 7);
    const int bChk = (lane >> 3) & 1;

    #pragma unroll
    for (int ks = 0; ks < 8; ks++) {
        uint32_t ah[2][4], al[2][4], bh[2][4], bl[2][4];
        #pragma unroll
        for (int mi = 0; mi < 2; mi++) {
            uint32_t off = sw128(m0w + mi * 16 + aRow, ks * 2 + aChk) * 2;
            ldm4(ah[mi], bxh + off);
            ldm4(al[mi], bxl + off);
        }
        uint32_t offb0 = sw128(n0w + bRow, ks * 2 + bChk) * 2;
        uint32_t offb1 = sw128(n0w + 16 + bRow, ks * 2 + bChk) * 2;
        // ---- V weight ----
        ldm4(bh[0], bVh + offb0); ldm4(bh[1], bVh + offb1);
        ldm4(bl[0], bVl + offb0); ldm4(bl[1], bVl + offb1);
        #pragma unroll
        for (int mi = 0; mi < 2; mi++) {
            mma16816(accV[mi][0], ah[mi], bh[0][0], bh[0][1]);
            mma16816(accV[mi][1], ah[mi], bh[0][2], bh[0][3]);
            mma16816(accV[mi][2], ah[mi], bh[1][0], bh[1][1]);
            mma16816(accV[mi][3], ah[mi], bh[1][2], bh[1][3]);
            mma16816(accV[mi][0], ah[mi], bl[0][0], bl[0][1]);
            mma16816(accV[mi][1], ah[mi], bl[0][2], bl[0][3]);
            mma16816(accV[mi][2], ah[mi], bl[1][0], bl[1][1]);
            mma16816(accV[mi][3], ah[mi], bl[1][2], bl[1][3]);
            mma16816(accV[mi][0], al[mi], bh[0][0], bh[0][1]);
            mma16816(accV[mi][1], al[mi], bh[0][2], bh[0][3]);
            mma16816(accV[mi][2], al[mi], bh[1][0], bh[1][1]);
            mma16816(accV[mi][3], al[mi], bh[1][2], bh[1][3]);
        }
        // ---- G weight ----
        ldm4(bh[0], bGh + offb0); ldm4(bh[1], bGh + offb1);
        ldm4(bl[0], bGl + offb0); ldm4(bl[1], bGl + offb1);
        #pragma unroll
        for (int mi = 0; mi < 2; mi++) {
            mma16816(accG[mi][0], ah[mi], bh[0][0], bh[0][1]);
            mma16816(accG[mi][1], ah[mi], bh[0][2], bh[0][3]);
            mma16816(accG[mi][2], ah[mi], bh[1][0], bh[1][1]);
            mma16816(accG[mi][3], ah[mi], bh[1][2], bh[1][3]);
            mma16816(accG[mi][0], ah[mi], bl[0][0], bl[0][1]);
            mma16816(accG[mi][1], ah[mi], bl[0][2], bl[0][3]);
            mma16816(accG[mi][2], ah[mi], bl[1][0], bl[1][1]);
            mma16816(accG[mi][3], ah[mi], bl[1][2], bl[1][3]);
            mma16816(accG[mi][0], al[mi], bh[0][0], bh[0][1]);
            mma16816(accG[mi][1], al[mi], bh[0][2], bh[0][3]);
            mma16816(accG[mi][2], al[mi], bh[1][0], bh[1][1]);
            mma16816(accG[mi][3], al[mi], bh[1][2], bh[1][3]);
        }
    }
}

// =====================================================================
// Kernel W: pre-split all 5 projection weights (unchanged)
// =====================================================================
__global__ void __launch_bounds__(256) kernW(
    const float* __restrict__ Wl, const float* __restrict__ Wlg,
    const float* __restrict__ Wr, const float* __restrict__ Wrg,
    const float* __restrict__ Wog)
{
    const float* W = (blockIdx.x == 0) ? Wl : (blockIdx.x == 1) ? Wlg :
                     (blockIdx.x == 2) ? Wr : (blockIdx.x == 3) ? Wrg : Wog;
    __nv_bfloat16* dh = g_wsp + (size_t)blockIdx.x * 32768;
    __nv_bfloat16* dl = dh + 16384;
    const int tid = threadIdx.x;
    #pragma unroll
    for (int t = 0; t < 16; t++) {
        int idx = tid + t * 256;
        int h = idx >> 5, kq = idx & 31;
        float4 w = *(const float4*)(W + h * 128 + kq * 4);
        __nv_bfloat162 h01 = __floats2bfloat162_rn(w.x, w.y);
        __nv_bfloat162 h23 = __floats2bfloat162_rn(w.z, w.w);
        __nv_bfloat162 l01 = __floats2bfloat162_rn(w.x - __bfloat162float(h01.x),
                                                   w.y - __bfloat162float(h01.y));
        __nv_bfloat162 l23 = __floats2bfloat162_rn(w.z - __bfloat162float(h23.x),
                                                   w.w - __bfloat162float(h23.y));
        uint32_t off = sw128(h, kq >> 1) + ((kq & 1) << 2);
        *(__nv_bfloat162*)(dh + off)     = h01;
        *(__nv_bfloat162*)(dh + off + 2) = h23;
        *(__nv_bfloat162*)(dl + off)     = l01;
        *(__nv_bfloat162*)(dl + off + 2) = l23;
    }
}

// =====================================================================
// Kernel A v5: LN + 5 projections + gating — fused V/G dual gemm
// 512 threads, 128 rows/block
// =====================================================================
struct SmemA5 {
    __nv_bfloat16 xh[128 * 128];        // 32 KB
    __nv_bfloat16 xl[128 * 128];        // 32 KB
    __nv_bfloat16 wbuf[2][32768];       // 2 x 64 KB (hi|lo)
    __nv_bfloat16 obf[128][130];        // 33.3 KB
    float mrow[128];
    float nw[128];
    float nb[128];
};

__global__ void __launch_bounds__(512, 1)
kernA(const float* __restrict__ x, const float* __restrict__ mask,
      const float* __restrict__ nw, const float* __restrict__ nb)
{
    extern __shared__ char raw[];
    SmemA5& sm = *reinterpret_cast<SmemA5*>(raw);
    const int tid = threadIdx.x;
    const int pos0 = blockIdx.x * 128;
    const int wid = tid >> 5, lid = tid & 31;

    const uint32_t bW = (uint32_t)__cvta_generic_to_shared(sm.wbuf);
    auto cpW = [&](int st, int w) {
        const __nv_bfloat16* src = g_wsp + (size_t)w * 32768;
        uint32_t dst = bW + (uint32_t)st * 65536;
        #pragma unroll
        for (int t = 0; t < 8; t++) {
            int c = tid + t * 512;
            cpa16(dst + c * 16, src + c * 8);
        }
        cpaCommit();
    };

    cpW(0, 0); cpW(1, 1);               // left pair in flight

    if (tid < 128) { sm.nw[tid] = nw[tid]; sm.nb[tid] = nb[tid]; sm.mrow[tid] = mask[pos0 + tid]; }
    __syncthreads();

    // LayerNorm: 16 warps x 8 rows
    #pragma unroll
    for (int rr = 0; rr < 8; rr++) {
        int r = wid * 8 + rr;
        float4 v = *(const float4*)(x + (size_t)(pos0 + r) * 128 + lid * 4);
        float s = v.x + v.y + v.z + v.w;
        float q = v.x * v.x + v.y * v.y + v.z * v.z + v.w * v.w;
        #pragma unroll
        for (int o = 16; o; o >>= 1) {
            s += __shfl_xor_sync(0xffffffffu, s, o);
            q += __shfl_xor_sync(0xffffffffu, q, o);
        }
        float mu = s * (1.f / 128.f);
        float rstd = rsqrtf(q * (1.f / 128.f) - mu * mu + 1e-5f);
        float4 nwv = *(const float4*)&sm.nw[lid * 4];
        float4 nbv = *(const float4*)&sm.nb[lid * 4];
        float y0 = (v.x - mu) * rstd * nwv.x + nbv.x;
        float y1 = (v.y - mu) * rstd * nwv.y + nbv.y;
        float y2 = (v.z - mu) * rstd * nwv.z + nbv.z;
        float y3 = (v.w - mu) * rstd * nwv.w + nbv.w;
        __nv_bfloat162 h01 = __floats2bfloat162_rn(y0, y1);
        __nv_bfloat162 h23 = __floats2bfloat162_rn(y2, y3);
        __nv_bfloat162 l01 = __floats2bfloat162_rn(y0 - __bfloat162float(h01.x),
                                                   y1 - __bfloat162float(h01.y));
        __nv_bfloat162 l23 = __floats2bfloat162_rn(y2 - __bfloat162float(h23.x),
                                                   y3 - __bfloat162float(h23.y));
        uint32_t off = sw128(r, lid >> 1) + ((lid & 1) << 2);
        *(__nv_bfloat162*)(sm.xh + off)     = h01;
        *(__nv_bfloat162*)(sm.xh + off + 2) = h23;
        *(__nv_bfloat162*)(sm.xl + off)     = l01;
        *(__nv_bfloat162*)(sm.xl + off + 2) = l23;
    }
    asm volatile("cp.async.wait_group 0;");
    __syncthreads();

    const int m0w = (wid >> 2) * 32;
    const int n0w = (wid & 3) * 32;
    const uint32_t bxh = (uint32_t)__cvta_generic_to_shared(sm.xh);
    const uint32_t bxl = (uint32_t)__cvta_generic_to_shared(sm.xl);
    float accV[2][4][4], accG[2][4][4];

    auto wbh = [&](int st) { return bW + (uint32_t)st * 65536; };
    auto wbl = [&](int st) { return bW + (uint32_t)st * 65536 + 32768; };

    auto combineFlush = [&](__nv_bfloat16* dst) {
        #pragma unroll
        for (int mt = 0; mt < 2; mt++) {
            int rA = m0w + mt * 16 + (lid >> 2);
            float mA = sm.mrow[rA], mB = sm.mrow[rA + 8];
            #pragma unroll
            for (int nt = 0; nt < 4; nt++) {
                int c = n0w + nt * 8 + 2 * (lid & 3);
                float v0 = accV[mt][nt][0] * mA * sigf(accG[mt][nt][0]);
                float v1 = accV[mt][nt][1] * mA * sigf(accG[mt][nt][1]);
                float v2 = accV[mt][nt][2] * mB * sigf(accG[mt][nt][2]);
                float v3 = accV[mt][nt][3] * mB * sigf(accG[mt][nt][3]);
                *(__nv_bfloat162*)&sm.obf[rA][c]     = __floats2bfloat162_rn(v0, v1);
                *(__nv_bfloat162*)&sm.obf[rA + 8][c] = __floats2bfloat162_rn(v2, v3);
            }
        }
        __syncthreads();
        #pragma unroll
        for (int t = 0; t < 32; t++) {
            int idx = tid + t * 512;
            int dch = idx >> 7, p = idx & 127;
            dst[(size_t)dch * NN + pos0 + p] = sm.obf[p][dch];
        }
        __syncthreads();
    };

    // ---- left: fused Wl(B0) + Wlg(B1)
    gemm3x2(accV, accG, m0w, n0w, lid, bxh, bxl, wbh(0), wbl(0), wbh(1), wbl(1));
    __syncthreads();                                      // weight reads done
    cpW(0, 2); cpW(1, 3);                                 // prefetch right pair over flush
    combineFlush(g_left);
    asm volatile("cp.async.wait_group 0;");
    __syncthreads();

    // ---- right: fused Wr(B0) + Wrg(B1)
    gemm3x2(accV, accG, m0w, n0w, lid, bxh, bxl, wbh(0), wbl(0), wbh(1), wbl(1));
    __syncthreads();
    cpW(0, 4);                                            // prefetch Wog over flush
    combineFlush(g_right);
    asm volatile("cp.async.wait_group 0;");
    __syncthreads();

    // ---- out_gate
    gemm3(accV, m0w, n0w, lid, bxh, bxl, wbh(0), wbl(0));
    #pragma unroll
    for (int mt = 0; mt < 2; mt++) {
        int rA = m0w + mt * 16 + (lid >> 2);
        #pragma unroll
        for (int nt = 0; nt < 4; nt++) {
            int c = n0w + nt * 8 + 2 * (lid & 3);
            float2 o0 = make_float2(sigf(accV[mt][nt][0]), sigf(accV[mt][nt][1]));
            float2 o1 = make_float2(sigf(accV[mt][nt][2]), sigf(accV[mt][nt][3]));
            *(float2*)(g_outgate + (size_t)(pos0 + rA) * 128 + c)     = o0;
            *(float2*)(g_outgate + (size_t)(pos0 + rA + 8) * 128 + c) = o1;
        }
    }
}

// =====================================================================
// Kernel B: per-channel batched GEMM (unchanged — passing)
// =====================================================================
__device__ __forceinline__ uint32_t swOff(int row, int chunk) {
    return (uint32_t)(row * 64 + ((chunk ^ (row & 7)) << 3));
}

__global__ void __launch_bounds__(256) kernB()
{
    extern __shared__ __nv_bfloat16 smb[];
    const int tid = threadIdx.x;
    const int d  = blockIdx.z;
    const int i0 = blockIdx.y * 128;
    const int j0 = blockIdx.x * 128;
    const __nv_bfloat16* A = g_left  + (size_t)d * NN;
    const __nv_bfloat16* B = g_right + (size_t)d * NN;

    const int warp = tid >> 5, lane = tid & 31;
    const int m0 = (warp >> 2) * 64;
    const int n0 = (warp & 3) * 32;
    const uint32_t base = (uint32_t)__cvta_generic_to_shared(smb);

    float acc[4][4][4];
    #pragma unroll
    for (int mi = 0; mi < 4; mi++)
        #pragma unroll
        for (int ni = 0; ni < 4; ni++)
            #pragma unroll
            for (int e = 0; e < 4; e++) acc[mi][ni][e] = 0.f;

    const int aRow = ((lane & 8) ? 8 : 0) + (lane & 7);
    const int aChk = (lane >> 4);
    const int bRow = ((lane & 16) ? 8 : 0) + (lane & 7);
    const int bChk = ((lane >> 3) & 1);

    auto loadTile = [&](int st, int kb) {
        uint32_t sbase = base + (uint32_t)st * 32768;
        #pragma unroll
        for (int t = 0; t < 4; t++) {
            int idx = tid + t * 256;
            int r = idx >> 3, c = idx & 7;
            uint32_t so = swOff(r, c) * 2;
            cpa16(sbase + so,         A + (size_t)(i0 + r) * NDIM + kb + c * 8);
            cpa16(sbase + 16384 + so, B + (size_t)(j0 + r) * NDIM + kb + c * 8);
        }
        cpaCommit();
    };

    loadTile(0, 0);
    #pragma unroll 1
    for (int k = 0; k < 6; k++) {
        const int cur = k & 1;
        if (k < 5) loadTile(1 - cur, (k + 1) * 64);
        if (k < 5) asm volatile("cp.async.wait_group 1;");
        else       asm volatile("cp.async.wait_group 0;");
        __syncthreads();

        const uint32_t sA = base + (uint32_t)cur * 32768;
        const uint32_t sB = sA + 16384;
        #pragma unroll
        for (int kk = 0; kk < 64; kk += 16) {
            uint32_t af[4][4];
            #pragma unroll
            for (int mi = 0; mi < 4; mi++) {
                int row = m0 + mi * 16 + aRow;
                ldm4(af[mi], sA + swOff(row, (kk >> 3) + aChk) * 2);
            }
            uint32_t bf[2][4];
            #pragma unroll
            for (int p = 0; p < 2; p++) {
                int row = n0 + p * 16 + bRow;
                ldm4(bf[p], sB + swOff(row, (kk >> 3) + bChk) * 2);
            }
            #pragma unroll
            for (int mi = 0; mi < 4; mi++) {
                mma16816(acc[mi][0], af[mi], bf[0][0], bf[0][1]);
                mma16816(acc[mi][1], af[mi], bf[0][2], bf[0][3]);
                mma16816(acc[mi][2], af[mi], bf[1][0], bf[1][1]);
                mma16816(acc[mi][3], af[mi], bf[1][2], bf[1][3]);
            }
        }
        __syncthreads();
    }

    __nv_bfloat16* C = g_accbf + (size_t)d * NN;
    const int r = lane >> 2, cp = (lane & 3) * 2;
    #pragma unroll
    for (int mi = 0; mi < 4; mi++)
        #pragma unroll
        for (int ni = 0; ni < 4; ni++) {
            int gi = i0 + m0 + mi * 16 + r;
            int gj = j0 + n0 + ni * 8 + cp;
            *(__nv_bfloat162*)(C + (size_t)gi * NDIM + gj) =
                __floats2bfloat162_rn(acc[mi][ni][0], acc[mi][ni][1]);
            *(__nv_bfloat162*)(C + (size_t)(gi + 8) * NDIM + gj) =
                __floats2bfloat162_rn(acc[mi][ni][2], acc[mi][ni][3]);
        }
}

// =====================================================================
// Kernel C: out-LN + out_gate + @W_out^T via bf16x3 HMMA
// pad 133 (conflict-free gather writes); scalar LN reads (alignment)
// =====================================================================
struct SmemC2 {
    __nv_bfloat16 xh[64 * 128];
    __nv_bfloat16 xl[64 * 128];
    union {
        float s[64][133];
        __nv_bfloat16 wh[128 * 128];
    };
    __nv_bfloat16 wl[128 * 128];
    float onw[128];
    float onb[128];
};

__device__ __forceinline__ void stageW4(__nv_bfloat16* wh, __nv_bfloat16* wl,
                                        const float* __restrict__ W, int tid) {
    #pragma unroll
    for (int t = 0; t < 16; t++) {
        int idx = tid + t * 256;
        int h = idx >> 5, kq = idx & 31;
        float4 w = *(const float4*)(W + h * 128 + kq * 4);
        __nv_bfloat162 h01 = __floats2bfloat162_rn(w.x, w.y);
        __nv_bfloat162 h23 = __floats2bfloat162_rn(w.z, w.w);
        __nv_bfloat162 l01 = __floats2bfloat162_rn(w.x - __bfloat162float(h01.x),
                                                   w.y - __bfloat162float(h01.y));
        __nv_bfloat162 l23 = __floats2bfloat162_rn(w.z - __bfloat162float(h23.x),
                                                   w.w - __bfloat162float(h23.y));
        uint32_t off = sw128(h, kq >> 1) + ((kq & 1) << 2);
        *(__nv_bfloat162*)(wh + off)     = h01;
        *(__nv_bfloat162*)(wh + off + 2) = h23;
        *(__nv_bfloat162*)(wl + off)     = l01;
        *(__nv_bfloat162*)(wl + off + 2) = l23;
    }
}

__global__ void __launch_bounds__(256, 2)
kernC(const float* __restrict__ onw, const float* __restrict__ onb,
      const float* __restrict__ Wout, float* __restrict__ out)
{
    extern __shared__ char raw[];
    SmemC2& sm = *reinterpret_cast<SmemC2*>(raw);
    const int tid = threadIdx.x;
    const int pos0 = blockIdx.x * 64;
    const int wid = tid >> 5, lid = tid & 31;

    if (tid < 128) { sm.onw[tid] = onw[tid]; sm.onb[tid] = onb[tid]; }
    #pragma unroll
    for (int t = 0; t < 32; t++) {
        int idx = tid + t * 256;
        int dch = idx >> 6, p = idx & 63;
        sm.s[p][dch] = __bfloat162float(g_accbf[(size_t)dch * NN + pos0 + p]);
    }
    __syncthreads();

    #pragma unroll
    for (int rr = 0; rr < 8; rr++) {
        int p = wid * 8 + rr;
        float v[4];
        #pragma unroll
        for (int t = 0; t < 4; t++) v[t] = sm.s[p][lid + 32 * t];
        float ssum = v[0] + v[1] + v[2] + v[3];
        float q = v[0]*v[0] + v[1]*v[1] + v[2]*v[2] + v[3]*v[3];
        #pragma unroll
        for (int o = 16; o; o >>= 1) {
            ssum += __shfl_xor_sync(0xffffffffu, ssum, o);
            q    += __shfl_xor_sync(0xffffffffu, q, o);
        }
        float mu = ssum * (1.f / 128.f);
        float rstd = rsqrtf(q * (1.f / 128.f) - mu * mu + 1e-5f);
        #pragma unroll
        for (int t = 0; t < 2; t++) {
            // process columns lid + 32t and lid + 32(t+2) as pairs? keep simple:
        }
        // gate + split, two bf162 per thread covering cols lid*? — use 4 scalar cols
        float y[4];
        const float* og = g_outgate + (size_t)(pos0 + p) * 128;
        #pragma unroll
        for (int t = 0; t < 4; t++) {
            int h = lid + 32 * t;
            y[t] = ((v[t] - mu) * rstd * sm.onw[h] + sm.onb[h]) * og[h];
        }
        // write fragments: this thread owns cols lid, lid+32, lid+64, lid+96 of row p
        #pragma unroll
        for (int t = 0; t < 4; t++) {
            int h = lid + 32 * t;
            __nv_bfloat16 hi = __float2bfloat16(y[t]);
            __nv_bfloat16 lo = __float2bfloat16(y[t] - __bfloat162float(hi));
            uint32_t off = sw128(p, h >> 3) + (h & 7);
            sm.xh[off] = hi;
            sm.xl[off] = lo;
        }
    }
    __syncthreads();

    stageW4(sm.wh, sm.wl, Wout, tid);
    __syncthreads();

    const int m0w = (wid >> 2) * 32;
    const int n0w = (wid & 3) * 32;
    const uint32_t bxh = (uint32_t)__cvta_generic_to_shared(sm.xh);
    const uint32_t bxl = (uint32_t)__cvta_generic_to_shared(sm.xl);
    const uint32_t bwh = (uint32_t)__cvta_generic_to_shared(sm.wh);
    const uint32_t bwl = (uint32_t)__cvta_generic_to_shared(sm.wl);
    float acc[2][4][4];
    gemm3(acc, m0w, n0w, lid, bxh, bxl, bwh, bwl);

    #pragma unroll
    for (int mt = 0; mt < 2; mt++) {
        int rA = m0w + mt * 16 + (lid >> 2);
        #pragma unroll
        for (int nt = 0; nt < 4; nt++) {
            int c = n0w + nt * 8 + 2 * (lid & 3);
            *(float2*)(out + (size_t)(pos0 + rA) * 128 + c) =
                make_float2(acc[mt][nt][0], acc[mt][nt][1]);
            *(float2*)(out + (size_t)(pos0 + rA + 8) * 128 + c) =
                make_float2(acc[mt][nt][2], acc[mt][nt][3]);
        }
    }
}

// =====================================================================
extern "C" void kernel_launch(void* const* d_in, const int* in_sizes, int n_in,
                              void* d_out, int out_size)
{
    (void)in_sizes; (void)n_in; (void)out_size;
    const float* x    = (const float*)d_in[0];
    const float* mask = (const float*)d_in[1];
    const float* nw   = (const float*)d_in[2];
    const float* nb   = (const float*)d_in[3];
    const float* Wl   = (const float*)d_in[4];
    const float* Wr   = (const float*)d_in[5];
    const float* Wlg  = (const float*)d_in[6];
    const float* Wrg  = (const float*)d_in[7];
    const float* Wog  = (const float*)d_in[8];
    const float* onw  = (const float*)d_in[9];
    const float* onb  = (const float*)d_in[10];
    const float* Wout = (const float*)d_in[11];
    float* out = (float*)d_out;

    cudaFuncSetAttribute(kernA, cudaFuncAttributeMaxDynamicSharedMemorySize, (int)sizeof(SmemA5));
    cudaFuncSetAttribute(kernB, cudaFuncAttributeMaxDynamicSharedMemorySize, 65536);
    cudaFuncSetAttribute(kernC, cudaFuncAttributeMaxDynamicSharedMemorySize, (int)sizeof(SmemC2));

    kernW<<<5, 256>>>(Wl, Wlg, Wr, Wrg, Wog);
    kernA<<<NN / 128, 512, sizeof(SmemA5)>>>(x, mask, nw, nb);
    kernB<<<dim3(3, 3, 128), 256, 65536>>>();
    kernC<<<NN / 64, 256, sizeof(SmemC2)>>>(onw, onb, Wout, out);
}

// round 15
// speedup vs baseline: 1.0098x; 1.0098x over previous
#include <cuda_runtime.h>
#include <cuda_bf16.h>
#include <cstdint>

#define NDIM 384
#define NN   (NDIM * NDIM)   // 147456
#define DDIM 128

// ---- scratch (device globals; no allocation allowed) ----
__device__ __nv_bfloat16 g_left [(size_t)DDIM * NN];   // [d][i*N+k] bf16
__device__ __nv_bfloat16 g_right[(size_t)DDIM * NN];   // [d][j*N+k] bf16
__device__ float         g_outgate[(size_t)NN * DDIM]; // [pos][h] fp32
__device__ __nv_bfloat16 g_accbf[(size_t)DDIM * NN];   // [d][i*N+j] bf16 (einsum out)
__device__ __nv_bfloat16 g_wsp[5 * 32768];             // pre-split weights, frag layout

__device__ __forceinline__ float sigf(float v) { return 1.f / (1.f + __expf(-v)); }

// ---- shared mma helpers ----
__device__ __forceinline__ void ldm4(uint32_t (&r)[4], uint32_t saddr) {
    asm volatile("ldmatrix.sync.aligned.m8n8.x4.shared.b16 {%0,%1,%2,%3}, [%4];"
        : "=r"(r[0]), "=r"(r[1]), "=r"(r[2]), "=r"(r[3]) : "r"(saddr));
}
__device__ __forceinline__ void mma16816(float (&d)[4], const uint32_t (&a)[4],
                                         uint32_t b0, uint32_t b1) {
    asm volatile("mma.sync.aligned.m16n8k16.row.col.f32.bf16.bf16.f32 "
        "{%0,%1,%2,%3}, {%4,%5,%6,%7}, {%8,%9}, {%0,%1,%2,%3};"
        : "+f"(d[0]), "+f"(d[1]), "+f"(d[2]), "+f"(d[3])
        : "r"(a[0]), "r"(a[1]), "r"(a[2]), "r"(a[3]), "r"(b0), "r"(b1));
}
__device__ __forceinline__ void cpa16(uint32_t dst, const void* src) {
    asm volatile("cp.async.cg.shared.global [%0], [%1], 16;" :: "r"(dst), "l"(src));
}
__device__ __forceinline__ void cpaCommit() { asm volatile("cp.async.commit_group;"); }

__device__ __forceinline__ uint32_t smem_u32(const void* p) {
    return (uint32_t)__cvta_generic_to_shared(p);
}

// 128-col swizzled offset (elements)
__device__ __forceinline__ uint32_t sw128(int row, int chunk) {
    return (uint32_t)(row * 128 + (((chunk & 7) ^ (row & 7)) << 3) + ((chunk & 8) << 3));
}

// 3-pass split gemm (bf16x3): one accumulator, 32x32 warp tile, K=128
__device__ __forceinline__ void gemm3(float acc[2][4][4], int m0w, int n0w, int lane,
                                      uint32_t bxh, uint32_t bxl,
                                      uint32_t bwh, uint32_t bwl) {
    #pragma unroll
    for (int mi = 0; mi < 2; mi++)
        #pragma unroll
        for (int ni = 0; ni < 4; ni++)
            #pragma unroll
            for (int e = 0; e < 4; e++) acc[mi][ni][e] = 0.f;

    const int aRow = ((lane & 8) ? 8 : 0) + (lane & 7);
    const int aChk = (lane >> 4);
    const int bRow = ((lane & 16) ? 8 : 0) + (lane & 7);
    const int bChk = (lane >> 3) & 1;

    #pragma unroll
    for (int ks = 0; ks < 8; ks++) {
        uint32_t ah[2][4], al[2][4], bh[2][4], bl[2][4];
        #pragma unroll
        for (int mi = 0; mi < 2; mi++) {
            uint32_t off = sw128(m0w + mi * 16 + aRow, ks * 2 + aChk) * 2;
            ldm4(ah[mi], bxh + off);
            ldm4(al[mi], bxl + off);
        }
        #pragma unroll
        for (int p = 0; p < 2; p++) {
            uint32_t off = sw128(n0w + p * 16 + bRow, ks * 2 + bChk) * 2;
            ldm4(bh[p], bwh + off);
            ldm4(bl[p], bwl + off);
        }
        #pragma unroll
        for (int mi = 0; mi < 2; mi++) {
            mma16816(acc[mi][0], ah[mi], bh[0][0], bh[0][1]);
            mma16816(acc[mi][1], ah[mi], bh[0][2], bh[0][3]);
            mma16816(acc[mi][2], ah[mi], bh[1][0], bh[1][1]);
            mma16816(acc[mi][3], ah[mi], bh[1][2], bh[1][3]);
            mma16816(acc[mi][0], ah[mi], bl[0][0], bl[0][1]);
            mma16816(acc[mi][1], ah[mi], bl[0][2], bl[0][3]);
            mma16816(acc[mi][2], ah[mi], bl[1][0], bl[1][1]);
            mma16816(acc[mi][3], ah[mi], bl[1][2], bl[1][3]);
            mma16816(acc[mi][0], al[mi], bh[0][0], bh[0][1]);
            mma16816(acc[mi][1], al[mi], bh[0][2], bh[0][3]);
            mma16816(acc[mi][2], al[mi], bh[1][0], bh[1][1]);
            mma16816(acc[mi][3], al[mi], bh[1][2], bh[1][3]);
        }
    }
}

// =====================================================================
// Kernel W: pre-split all 5 projection weights (unchanged — passing)
// =====================================================================
__global__ void __launch_bounds__(256) kernW(
    const float* __restrict__ Wl, const float* __restrict__ Wlg,
    const float* __restrict__ Wr, const float* __restrict__ Wrg,
    const float* __restrict__ Wog)
{
    const float* W = (blockIdx.x == 0) ? Wl : (blockIdx.x == 1) ? Wlg :
                     (blockIdx.x == 2) ? Wr : (blockIdx.x == 3) ? Wrg : Wog;
    __nv_bfloat16* dh = g_wsp + (size_t)blockIdx.x * 32768;
    __nv_bfloat16* dl = dh + 16384;
    const int tid = threadIdx.x;
    #pragma unroll
    for (int t = 0; t < 16; t++) {
        int idx = tid + t * 256;
        int h = idx >> 5, kq = idx & 31;
        float4 w = *(const float4*)(W + h * 128 + kq * 4);
        __nv_bfloat162 h01 = __floats2bfloat162_rn(w.x, w.y);
        __nv_bfloat162 h23 = __floats2bfloat162_rn(w.z, w.w);
        __nv_bfloat162 l01 = __floats2bfloat162_rn(w.x - __bfloat162float(h01.x),
                                                   w.y - __bfloat162float(h01.y));
        __nv_bfloat162 l23 = __floats2bfloat162_rn(w.z - __bfloat162float(h23.x),
                                                   w.w - __bfloat162float(h23.y));
        uint32_t off = sw128(h, kq >> 1) + ((kq & 1) << 2);
        *(__nv_bfloat162*)(dh + off)     = h01;
        *(__nv_bfloat162*)(dh + off + 2) = h23;
        *(__nv_bfloat162*)(dl + off)     = l01;
        *(__nv_bfloat162*)(dl + off + 2) = l23;
    }
}

// =====================================================================
// Kernel A (R11 version — measured 242 us): LN + 5 projections + gating
// 512 threads, 128 rows/block, double-buffered cp.async weight stream
// =====================================================================
struct SmemA5 {
    __nv_bfloat16 xh[128 * 128];
    __nv_bfloat16 xl[128 * 128];
    __nv_bfloat16 wbuf[2][32768];
    __nv_bfloat16 obf[128][130];
    float mrow[128];
    float nw[128];
    float nb[128];
};

__global__ void __launch_bounds__(512, 1)
kernA(const float* __restrict__ x, const float* __restrict__ mask,
      const float* __restrict__ nw, const float* __restrict__ nb)
{
    extern __shared__ char raw[];
    SmemA5& sm = *reinterpret_cast<SmemA5*>(raw);
    const int tid = threadIdx.x;
    const int pos0 = blockIdx.x * 128;
    const int wid = tid >> 5, lid = tid & 31;

    const uint32_t bW = smem_u32(sm.wbuf);
    auto cpW = [&](int st, int w) {
        const __nv_bfloat16* src = g_wsp + (size_t)w * 32768;
        uint32_t dst = bW + (uint32_t)st * 65536;
        #pragma unroll
        for (int t = 0; t < 8; t++) {
            int c = tid + t * 512;
            cpa16(dst + c * 16, src + c * 8);
        }
        cpaCommit();
    };

    cpW(0, 0);

    if (tid < 128) { sm.nw[tid] = nw[tid]; sm.nb[tid] = nb[tid]; sm.mrow[tid] = mask[pos0 + tid]; }
    __syncthreads();

    #pragma unroll
    for (int rr = 0; rr < 8; rr++) {
        int r = wid * 8 + rr;
        float4 v = *(const float4*)(x + (size_t)(pos0 + r) * 128 + lid * 4);
        float s = v.x + v.y + v.z + v.w;
        float q = v.x * v.x + v.y * v.y + v.z * v.z + v.w * v.w;
        #pragma unroll
        for (int o = 16; o; o >>= 1) {
            s += __shfl_xor_sync(0xffffffffu, s, o);
            q += __shfl_xor_sync(0xffffffffu, q, o);
        }
        float mu = s * (1.f / 128.f);
        float rstd = rsqrtf(q * (1.f / 128.f) - mu * mu + 1e-5f);
        float4 nwv = *(const float4*)&sm.nw[lid * 4];
        float4 nbv = *(const float4*)&sm.nb[lid * 4];
        float y0 = (v.x - mu) * rstd * nwv.x + nbv.x;
        float y1 = (v.y - mu) * rstd * nwv.y + nbv.y;
        float y2 = (v.z - mu) * rstd * nwv.z + nbv.z;
        float y3 = (v.w - mu) * rstd * nwv.w + nbv.w;
        __nv_bfloat162 h01 = __floats2bfloat162_rn(y0, y1);
        __nv_bfloat162 h23 = __floats2bfloat162_rn(y2, y3);
        __nv_bfloat162 l01 = __floats2bfloat162_rn(y0 - __bfloat162float(h01.x),
                                                   y1 - __bfloat162float(h01.y));
        __nv_bfloat162 l23 = __floats2bfloat162_rn(y2 - __bfloat162float(h23.x),
                                                   y3 - __bfloat162float(h23.y));
        uint32_t off = sw128(r, lid >> 1) + ((lid & 1) << 2);
        *(__nv_bfloat162*)(sm.xh + off)     = h01;
        *(__nv_bfloat162*)(sm.xh + off + 2) = h23;
        *(__nv_bfloat162*)(sm.xl + off)     = l01;
        *(__nv_bfloat162*)(sm.xl + off + 2) = l23;
    }
    asm volatile("cp.async.wait_group 0;");
    __syncthreads();

    const int m0w = (wid >> 2) * 32;
    const int n0w = (wid & 3) * 32;
    const uint32_t bxh = smem_u32(sm.xh);
    const uint32_t bxl = smem_u32(sm.xl);
    float accV[2][4][4], accG[2][4][4];

    auto wbh = [&](int st) { return bW + (uint32_t)st * 65536; };
    auto wbl = [&](int st) { return bW + (uint32_t)st * 65536 + 32768; };

    auto combineFlush = [&](__nv_bfloat16* dst) {
        #pragma unroll
        for (int mt = 0; mt < 2; mt++) {
            int rA = m0w + mt * 16 + (lid >> 2);
            float mA = sm.mrow[rA], mB = sm.mrow[rA + 8];
            #pragma unroll
            for (int nt = 0; nt < 4; nt++) {
                int c = n0w + nt * 8 + 2 * (lid & 3);
                float v0 = accV[mt][nt][0] * mA * sigf(accG[mt][nt][0]);
                float v1 = accV[mt][nt][1] * mA * sigf(accG[mt][nt][1]);
                float v2 = accV[mt][nt][2] * mB * sigf(accG[mt][nt][2]);
                float v3 = accV[mt][nt][3] * mB * sigf(accG[mt][nt][3]);
                *(__nv_bfloat162*)&sm.obf[rA][c]     = __floats2bfloat162_rn(v0, v1);
                *(__nv_bfloat162*)&sm.obf[rA + 8][c] = __floats2bfloat162_rn(v2, v3);
            }
        }
        __syncthreads();
        #pragma unroll
        for (int t = 0; t < 32; t++) {
            int idx = tid + t * 512;
            int dch = idx >> 7, p = idx & 127;
            dst[(size_t)dch * NN + pos0 + p] = sm.obf[p][dch];
        }
        __syncthreads();
    };

    // ---- left pair
    cpW(1, 1);
    gemm3(accV, m0w, n0w, lid, bxh, bxl, wbh(0), wbl(0));
    __syncthreads();
    cpW(0, 2);
    asm volatile("cp.async.wait_group 1;");
    __syncthreads();
    gemm3(accG, m0w, n0w, lid, bxh, bxl, wbh(1), wbl(1));
    combineFlush(g_left);

    // ---- right pair
    cpW(1, 3);
    asm volatile("cp.async.wait_group 1;");
    __syncthreads();
    gemm3(accV, m0w, n0w, lid, bxh, bxl, wbh(0), wbl(0));
    __syncthreads();
    cpW(0, 4);
    asm volatile("cp.async.wait_group 1;");
    __syncthreads();
    gemm3(accG, m0w, n0w, lid, bxh, bxl, wbh(1), wbl(1));
    combineFlush(g_right);

    // ---- out_gate
    asm volatile("cp.async.wait_group 0;");
    __syncthreads();
    gemm3(accV, m0w, n0w, lid, bxh, bxl, wbh(0), wbl(0));
    #pragma unroll
    for (int mt = 0; mt < 2; mt++) {
        int rA = m0w + mt * 16 + (lid >> 2);
        #pragma unroll
        for (int nt = 0; nt < 4; nt++) {
            int c = n0w + nt * 8 + 2 * (lid & 3);
            float2 o0 = make_float2(sigf(accV[mt][nt][0]), sigf(accV[mt][nt][1]));
            float2 o1 = make_float2(sigf(accV[mt][nt][2]), sigf(accV[mt][nt][3]));
            *(float2*)(g_outgate + (size_t)(pos0 + rA) * 128 + c)     = o0;
            *(float2*)(g_outgate + (size_t)(pos0 + rA + 8) * 128 + c) = o1;
        }
    }
}

// =====================================================================
// Kernel B: per-channel batched GEMM — R10 HMMA cp.async version
// =====================================================================
__device__ __forceinline__ uint32_t swOff(int row, int chunk) {
    return (uint32_t)(row * 64 + ((chunk ^ (row & 7)) << 3));
}

__global__ void __launch_bounds__(256) kernB()
{
    extern __shared__ __nv_bfloat16 smb[];
    const int tid = threadIdx.x;
    const int d  = blockIdx.z;
    const int i0 = blockIdx.y * 128;
    const int j0 = blockIdx.x * 128;
    const __nv_bfloat16* A = g_left  + (size_t)d * NN;
    const __nv_bfloat16* B = g_right + (size_t)d * NN;

    const int warp = tid >> 5, lane = tid & 31;
    const int m0 = (warp >> 2) * 64;
    const int n0 = (warp & 3) * 32;
    const uint32_t base = smem_u32(smb);

    float acc[4][4][4];
    #pragma unroll
    for (int mi = 0; mi < 4; mi++)
        #pragma unroll
        for (int ni = 0; ni < 4; ni++)
            #pragma unroll
            for (int e = 0; e < 4; e++) acc[mi][ni][e] = 0.f;

    const int aRow = ((lane & 8) ? 8 : 0) + (lane & 7);
    const int aChk = (lane >> 4);
    const int bRow = ((lane & 16) ? 8 : 0) + (lane & 7);
    const int bChk = ((lane >> 3) & 1);

    auto loadTile = [&](int st, int kb) {
        uint32_t sbase = base + (uint32_t)st * 32768;
        #pragma unroll
        for (int t = 0; t < 4; t++) {
            int idx = tid + t * 256;
            int r = idx >> 3, c = idx & 7;
            uint32_t so = swOff(r, c) * 2;
            cpa16(sbase + so,         A + (size_t)(i0 + r) * NDIM + kb + c * 8);
            cpa16(sbase + 16384 + so, B + (size_t)(j0 + r) * NDIM + kb + c * 8);
        }
        cpaCommit();
    };

    loadTile(0, 0);
    #pragma unroll 1
    for (int k = 0; k < 6; k++) {
        const int cur = k & 1;
        if (k < 5) loadTile(1 - cur, (k + 1) * 64);
        if (k < 5) asm volatile("cp.async.wait_group 1;");
        else       asm volatile("cp.async.wait_group 0;");
        __syncthreads();

        const uint32_t sA = base + (uint32_t)cur * 32768;
        const uint32_t sB = sA + 16384;
        #pragma unroll
        for (int kk = 0; kk < 64; kk += 16) {
            uint32_t af[4][4];
            #pragma unroll
            for (int mi = 0; mi < 4; mi++) {
                int row = m0 + mi * 16 + aRow;
                ldm4(af[mi], sA + swOff(row, (kk >> 3) + aChk) * 2);
            }
            uint32_t bf[2][4];
            #pragma unroll
            for (int p = 0; p < 2; p++) {
                int row = n0 + p * 16 + bRow;
                ldm4(bf[p], sB + swOff(row, (kk >> 3) + bChk) * 2);
            }
            #pragma unroll
            for (int mi = 0; mi < 4; mi++) {
                mma16816(acc[mi][0], af[mi], bf[0][0], bf[0][1]);
                mma16816(acc[mi][1], af[mi], bf[0][2], bf[0][3]);
                mma16816(acc[mi][2], af[mi], bf[1][0], bf[1][1]);
                mma16816(acc[mi][3], af[mi], bf[1][2], bf[1][3]);
            }
        }
        __syncthreads();
    }

    __nv_bfloat16* C = g_accbf + (size_t)d * NN;
    const int r = lane >> 2, cp = (lane & 3) * 2;
    #pragma unroll
    for (int mi = 0; mi < 4; mi++)
        #pragma unroll
        for (int ni = 0; ni < 4; ni++) {
            int gi = i0 + m0 + mi * 16 + r;
            int gj = j0 + n0 + ni * 8 + cp;
            *(__nv_bfloat162*)(C + (size_t)gi * NDIM + gj) =
                __floats2bfloat162_rn(acc[mi][ni][0], acc[mi][ni][1]);
            *(__nv_bfloat162*)(C + (size_t)(gi + 8) * NDIM + gj) =
                __floats2bfloat162_rn(acc[mi][ni][2], acc[mi][ni][3]);
        }
}

// =====================================================================
// Kernel C v3: out-LN + out_gate + @W_out^T via bf16x3 HMMA
// cp.async bf16 gather staging in wl (no fp32 round-trip, coalesced)
// =====================================================================
struct SmemC3 {
    __nv_bfloat16 xh[64 * 128];     // 16 KB  activation hi frags
    __nv_bfloat16 xl[64 * 128];     // 16 KB  activation lo frags
    __nv_bfloat16 wh[128 * 128];    // 32 KB  W_out hi frags
    __nv_bfloat16 wl[128 * 128];    // 32 KB  W_out lo frags; first 18.4KB doubles
                                    //        as bf16 gather stage [dch][72]
    float onw[128];
    float onb[128];
};  // ~97 KB -> 2 CTAs/SM

__device__ __forceinline__ void stageW4(__nv_bfloat16* wh, __nv_bfloat16* wl,
                                        const float* __restrict__ W, int tid) {
    #pragma unroll
    for (int t = 0; t < 16; t++) {
        int idx = tid + t * 256;
        int h = idx >> 5, kq = idx & 31;
        float4 w = *(const float4*)(W + h * 128 + kq * 4);
        __nv_bfloat162 h01 = __floats2bfloat162_rn(w.x, w.y);
        __nv_bfloat162 h23 = __floats2bfloat162_rn(w.z, w.w);
        __nv_bfloat162 l01 = __floats2bfloat162_rn(w.x - __bfloat162float(h01.x),
                                                   w.y - __bfloat162float(h01.y));
        __nv_bfloat162 l23 = __floats2bfloat162_rn(w.z - __bfloat162float(h23.x),
                                                   w.w - __bfloat162float(h23.y));
        uint32_t off = sw128(h, kq >> 1) + ((kq & 1) << 2);
        *(__nv_bfloat162*)(wh + off)     = h01;
        *(__nv_bfloat162*)(wh + off + 2) = h23;
        *(__nv_bfloat162*)(wl + off)     = l01;
        *(__nv_bfloat162*)(wl + off + 2) = l23;
    }
}

__global__ void __launch_bounds__(256, 2)
kernC(const float* __restrict__ onw, const float* __restrict__ onb,
      const float* __restrict__ Wout, float* __restrict__ out)
{
    extern __shared__ char raw[];
    SmemC3& sm = *reinterpret_cast<SmemC3*>(raw);
    const int tid = threadIdx.x;
    const int pos0 = blockIdx.x * 64;
    const int wid = tid >> 5, lid = tid & 31;

    // coalesced cp.async gather of the 64x128 bf16 tile into wl-stage:
    // stage[dch][p] with row stride 72 elements (144 B, 16B-aligned rows)
    const uint32_t bstage = smem_u32(sm.wl);
    #pragma unroll
    for (int t = 0; t < 4; t++) {
        int u = tid + t * 256;               // 16B chunk: 128 dch x 8 chunks
        int dch = u >> 3, p0 = (u & 7) * 8;
        cpa16(bstage + (uint32_t)(dch * 72 + p0) * 2,
              g_accbf + (size_t)dch * NN + pos0 + p0);
    }
    cpaCommit();

    if (tid < 128) { sm.onw[tid] = onw[tid]; sm.onb[tid] = onb[tid]; }
    asm volatile("cp.async.wait_group 0;");
    __syncthreads();

    // out-LN + gate + hi/lo split (warp wid -> rows wid*8..+7)
    #pragma unroll
    for (int rr = 0; rr < 8; rr++) {
        int p = wid * 8 + rr;
        float v[4];
        #pragma unroll
        for (int t = 0; t < 4; t++) {
            int dch = lid + 32 * t;
            v[t] = __bfloat162float(sm.wl[dch * 72 + p]);
        }
        float ssum = v[0] + v[1] + v[2] + v[3];
        float q = v[0]*v[0] + v[1]*v[1] + v[2]*v[2] + v[3]*v[3];
        #pragma unroll
        for (int o = 16; o; o >>= 1) {
            ssum += __shfl_xor_sync(0xffffffffu, ssum, o);
            q    += __shfl_xor_sync(0xffffffffu, q, o);
        }
        float mu = ssum * (1.f / 128.f);
        float rstd = rsqrtf(q * (1.f / 128.f) - mu * mu + 1e-5f);
        const float* og = g_outgate + (size_t)(pos0 + p) * 128;
        #pragma unroll
        for (int t = 0; t < 4; t++) {
            int h = lid + 32 * t;
            float y = ((v[t] - mu) * rstd * sm.onw[h] + sm.onb[h]) * og[h];
            __nv_bfloat16 hi = __float2bfloat16(y);
            __nv_bfloat16 lo = __float2bfloat16(y - __bfloat162float(hi));
            uint32_t off = sw128(p, h >> 3) + (h & 7);
            sm.xh[off] = hi;
            sm.xl[off] = lo;
        }
    }
    __syncthreads();                 // all stage reads done before wl overwrite

    stageW4(sm.wh, sm.wl, Wout, tid);
    __syncthreads();

    const int m0w = (wid >> 2) * 32;
    const int n0w = (wid & 3) * 32;
    const uint32_t bxh = smem_u32(sm.xh);
    const uint32_t bxl = smem_u32(sm.xl);
    const uint32_t bwh = smem_u32(sm.wh);
    const uint32_t bwl = smem_u32(sm.wl);
    float acc[2][4][4];
    gemm3(acc, m0w, n0w, lid, bxh, bxl, bwh, bwl);

    #pragma unroll
    for (int mt = 0; mt < 2; mt++) {
        int rA = m0w + mt * 16 + (lid >> 2);
        #pragma unroll
        for (int nt = 0; nt < 4; nt++) {
            int c = n0w + nt * 8 + 2 * (lid & 3);
            *(float2*)(out + (size_t)(pos0 + rA) * 128 + c) =
                make_float2(acc[mt][nt][0], acc[mt][nt][1]);
            *(float2*)(out + (size_t)(pos0 + rA + 8) * 128 + c) =
                make_float2(acc[mt][nt][2], acc[mt][nt][3]);
        }
    }
}

// =====================================================================
extern "C" void kernel_launch(void* const* d_in, const int* in_sizes, int n_in,
                              void* d_out, int out_size)
{
    (void)in_sizes; (void)n_in; (void)out_size;
    const float* x    = (const float*)d_in[0];
    const float* mask = (const float*)d_in[1];
    const float* nw   = (const float*)d_in[2];
    const float* nb   = (const float*)d_in[3];
    const float* Wl   = (const float*)d_in[4];
    const float* Wr   = (const float*)d_in[5];
    const float* Wlg  = (const float*)d_in[6];
    const float* Wrg  = (const float*)d_in[7];
    const float* Wog  = (const float*)d_in[8];
    const float* onw  = (const float*)d_in[9];
    const float* onb  = (const float*)d_in[10];
    const float* Wout = (const float*)d_in[11];
    float* out = (float*)d_out;

    cudaFuncSetAttribute(kernA, cudaFuncAttributeMaxDynamicSharedMemorySize, (int)sizeof(SmemA5));
    cudaFuncSetAttribute(kernB, cudaFuncAttributeMaxDynamicSharedMemorySize, 65536);
    cudaFuncSetAttribute(kernC, cudaFuncAttributeMaxDynamicSharedMemorySize, (int)sizeof(SmemC3));

    kernW<<<5, 256>>>(Wl, Wlg, Wr, Wrg, Wog);
    kernA<<<NN / 128, 512, sizeof(SmemA5)>>>(x, mask, nw, nb);
    kernB<<<dim3(3, 3, 128), 256, 65536>>>();
    kernC<<<NN / 64, 256, sizeof(SmemC3)>>>(onw, onb, Wout, out);
}

// round 16
// speedup vs baseline: 1.1161x; 1.1053x over previous
#include <cuda_runtime.h>
#include <cuda_bf16.h>
#include <cstdint>

#define NDIM 384
#define NN   (NDIM * NDIM)   // 147456
#define DDIM 128

// ---- scratch (device globals; no allocation allowed) ----
__device__ __nv_bfloat16 g_left [(size_t)DDIM * NN];   // [d][i*N+k] bf16
__device__ __nv_bfloat16 g_right[(size_t)DDIM * NN];   // [d][j*N+k] bf16
__device__ float         g_outgate[(size_t)NN * DDIM]; // [pos][h] fp32
__device__ __nv_bfloat16 g_accbf[(size_t)DDIM * NN];   // [d][i*N+j] bf16 (einsum out)
__device__ __nv_bfloat16 g_wsp[6 * 32768];             // pre-split weights, frag layout
                                                       // [w]: 0..4 proj, 5=Wout

__device__ __forceinline__ float sigf(float v) { return 1.f / (1.f + __expf(-v)); }

// ---- shared mma helpers ----
__device__ __forceinline__ void ldm4(uint32_t (&r)[4], uint32_t saddr) {
    asm volatile("ldmatrix.sync.aligned.m8n8.x4.shared.b16 {%0,%1,%2,%3}, [%4];"
        : "=r"(r[0]), "=r"(r[1]), "=r"(r[2]), "=r"(r[3]) : "r"(saddr));
}
__device__ __forceinline__ void mma16816(float (&d)[4], const uint32_t (&a)[4],
                                         uint32_t b0, uint32_t b1) {
    asm volatile("mma.sync.aligned.m16n8k16.row.col.f32.bf16.bf16.f32 "
        "{%0,%1,%2,%3}, {%4,%5,%6,%7}, {%8,%9}, {%0,%1,%2,%3};"
        : "+f"(d[0]), "+f"(d[1]), "+f"(d[2]), "+f"(d[3])
        : "r"(a[0]), "r"(a[1]), "r"(a[2]), "r"(a[3]), "r"(b0), "r"(b1));
}
__device__ __forceinline__ void cpa16(uint32_t dst, const void* src) {
    asm volatile("cp.async.cg.shared.global [%0], [%1], 16;" :: "r"(dst), "l"(src));
}
__device__ __forceinline__ void cpaCommit() { asm volatile("cp.async.commit_group;"); }

__device__ __forceinline__ uint32_t smem_u32(const void* p) {
    return (uint32_t)__cvta_generic_to_shared(p);
}

// 128-col swizzled offset (elements)
__device__ __forceinline__ uint32_t sw128(int row, int chunk) {
    return (uint32_t)(row * 128 + (((chunk & 7) ^ (row & 7)) << 3) + ((chunk & 8) << 3));
}

// 3-pass split gemm (bf16x3): one accumulator, 32x32 warp tile, K=128
__device__ __forceinline__ void gemm3(float acc[2][4][4], int m0w, int n0w, int lane,
                                      uint32_t bxh, uint32_t bxl,
                                      uint32_t bwh, uint32_t bwl) {
    #pragma unroll
    for (int mi = 0; mi < 2; mi++)
        #pragma unroll
        for (int ni = 0; ni < 4; ni++)
            #pragma unroll
            for (int e = 0; e < 4; e++) acc[mi][ni][e] = 0.f;

    const int aRow = ((lane & 8) ? 8 : 0) + (lane & 7);
    const int aChk = (lane >> 4);
    const int bRow = ((lane & 16) ? 8 : 0) + (lane & 7);
    const int bChk = (lane >> 3) & 1;

    #pragma unroll
    for (int ks = 0; ks < 8; ks++) {
        uint32_t ah[2][4], al[2][4], bh[2][4], bl[2][4];
        #pragma unroll
        for (int mi = 0; mi < 2; mi++) {
            uint32_t off = sw128(m0w + mi * 16 + aRow, ks * 2 + aChk) * 2;
            ldm4(ah[mi], bxh + off);
            ldm4(al[mi], bxl + off);
        }
        #pragma unroll
        for (int p = 0; p < 2; p++) {
            uint32_t off = sw128(n0w + p * 16 + bRow, ks * 2 + bChk) * 2;
            ldm4(bh[p], bwh + off);
            ldm4(bl[p], bwl + off);
        }
        #pragma unroll
        for (int mi = 0; mi < 2; mi++) {
            mma16816(acc[mi][0], ah[mi], bh[0][0], bh[0][1]);
            mma16816(acc[mi][1], ah[mi], bh[0][2], bh[0][3]);
            mma16816(acc[mi][2], ah[mi], bh[1][0], bh[1][1]);
            mma16816(acc[mi][3], ah[mi], bh[1][2], bh[1][3]);
            mma16816(acc[mi][0], ah[mi], bl[0][0], bl[0][1]);
            mma16816(acc[mi][1], ah[mi], bl[0][2], bl[0][3]);
            mma16816(acc[mi][2], ah[mi], bl[1][0], bl[1][1]);
            mma16816(acc[mi][3], ah[mi], bl[1][2], bl[1][3]);
            mma16816(acc[mi][0], al[mi], bh[0][0], bh[0][1]);
            mma16816(acc[mi][1], al[mi], bh[0][2], bh[0][3]);
            mma16816(acc[mi][2], al[mi], bh[1][0], bh[1][1]);
            mma16816(acc[mi][3], al[mi], bh[1][2], bh[1][3]);
        }
    }
}

// =====================================================================
// Kernel W: pre-split all 6 weights into bf16 hi/lo frag layout
// =====================================================================
__global__ void __launch_bounds__(256) kernW(
    const float* __restrict__ Wl, const float* __restrict__ Wlg,
    const float* __restrict__ Wr, const float* __restrict__ Wrg,
    const float* __restrict__ Wog, const float* __restrict__ Wout)
{
    const float* W = (blockIdx.x == 0) ? Wl : (blockIdx.x == 1) ? Wlg :
                     (blockIdx.x == 2) ? Wr : (blockIdx.x == 3) ? Wrg :
                     (blockIdx.x == 4) ? Wog : Wout;
    __nv_bfloat16* dh = g_wsp + (size_t)blockIdx.x * 32768;
    __nv_bfloat16* dl = dh + 16384;
    const int tid = threadIdx.x;
    #pragma unroll
    for (int t = 0; t < 16; t++) {
        int idx = tid + t * 256;
        int h = idx >> 5, kq = idx & 31;
        float4 w = *(const float4*)(W + h * 128 + kq * 4);
        __nv_bfloat162 h01 = __floats2bfloat162_rn(w.x, w.y);
        __nv_bfloat162 h23 = __floats2bfloat162_rn(w.z, w.w);
        __nv_bfloat162 l01 = __floats2bfloat162_rn(w.x - __bfloat162float(h01.x),
                                                   w.y - __bfloat162float(h01.y));
        __nv_bfloat162 l23 = __floats2bfloat162_rn(w.z - __bfloat162float(h23.x),
                                                   w.w - __bfloat162float(h23.y));
        uint32_t off = sw128(h, kq >> 1) + ((kq & 1) << 2);
        *(__nv_bfloat162*)(dh + off)     = h01;
        *(__nv_bfloat162*)(dh + off + 2) = h23;
        *(__nv_bfloat162*)(dl + off)     = l01;
        *(__nv_bfloat162*)(dl + off + 2) = l23;
    }
}

// =====================================================================
// Kernel A v6: LN + 5 projections + gating — 64 rows, 256 thr,
// pre-split weights, single weight buffer (obf aliased), 2 CTAs/SM
// =====================================================================
struct SmemA6 {
    __nv_bfloat16 xh[64 * 128];          // 16 KB
    __nv_bfloat16 xl[64 * 128];          // 16 KB
    union {
        __nv_bfloat16 wbuf[32768];       // 64 KB: hi [0,16384) lo [16384,32768)
        __nv_bfloat16 obf[64][130];      // 16.6 KB (aliases wbuf)
    };
    float mrow[64];
    float nw[128];
    float nb[128];
};  // ~97.4 KB -> 2 CTAs/SM

__global__ void __launch_bounds__(256, 2)
kernA(const float* __restrict__ x, const float* __restrict__ mask,
      const float* __restrict__ nw, const float* __restrict__ nb)
{
    extern __shared__ char raw[];
    SmemA6& sm = *reinterpret_cast<SmemA6*>(raw);
    const int tid = threadIdx.x;
    const int pos0 = blockIdx.x * 64;
    const int wid = tid >> 5, lid = tid & 31;

    const uint32_t bW = smem_u32(sm.wbuf);
    auto cpW = [&](int w) {                    // copy pre-split weight w into wbuf
        const __nv_bfloat16* src = g_wsp + (size_t)w * 32768;
        #pragma unroll
        for (int t = 0; t < 16; t++) {
            int c = tid + t * 256;             // 16B chunk, 4096 total
            cpa16(bW + c * 16, src + c * 8);
        }
        cpaCommit();
    };

    cpW(0);                                    // Wl in flight over LN

    if (tid < 128) { sm.nw[tid] = nw[tid]; sm.nb[tid] = nb[tid]; }
    if (tid < 64)  sm.mrow[tid] = mask[pos0 + tid];
    __syncthreads();

    // LayerNorm: 8 warps x 8 rows = 64 rows
    #pragma unroll
    for (int rr = 0; rr < 8; rr++) {
        int r = wid * 8 + rr;
        float4 v = *(const float4*)(x + (size_t)(pos0 + r) * 128 + lid * 4);
        float s = v.x + v.y + v.z + v.w;
        float q = v.x * v.x + v.y * v.y + v.z * v.z + v.w * v.w;
        #pragma unroll
        for (int o = 16; o; o >>= 1) {
            s += __shfl_xor_sync(0xffffffffu, s, o);
            q += __shfl_xor_sync(0xffffffffu, q, o);
        }
        float mu = s * (1.f / 128.f);
        float rstd = rsqrtf(q * (1.f / 128.f) - mu * mu + 1e-5f);
        float4 nwv = *(const float4*)&sm.nw[lid * 4];
        float4 nbv = *(const float4*)&sm.nb[lid * 4];
        float y0 = (v.x - mu) * rstd * nwv.x + nbv.x;
        float y1 = (v.y - mu) * rstd * nwv.y + nbv.y;
        float y2 = (v.z - mu) * rstd * nwv.z + nbv.z;
        float y3 = (v.w - mu) * rstd * nwv.w + nbv.w;
        __nv_bfloat162 h01 = __floats2bfloat162_rn(y0, y1);
        __nv_bfloat162 h23 = __floats2bfloat162_rn(y2, y3);
        __nv_bfloat162 l01 = __floats2bfloat162_rn(y0 - __bfloat162float(h01.x),
                                                   y1 - __bfloat162float(h01.y));
        __nv_bfloat162 l23 = __floats2bfloat162_rn(y2 - __bfloat162float(h23.x),
                                                   y3 - __bfloat162float(h23.y));
        uint32_t off = sw128(r, lid >> 1) + ((lid & 1) << 2);
        *(__nv_bfloat162*)(sm.xh + off)     = h01;
        *(__nv_bfloat162*)(sm.xh + off + 2) = h23;
        *(__nv_bfloat162*)(sm.xl + off)     = l01;
        *(__nv_bfloat162*)(sm.xl + off + 2) = l23;
    }
    asm volatile("cp.async.wait_group 0;");    // Wl resident
    __syncthreads();

    const int m0w = (wid >> 2) * 32;           // 0 or 32
    const int n0w = (wid & 3) * 32;            // 0..96
    const uint32_t bxh = smem_u32(sm.xh);
    const uint32_t bxl = smem_u32(sm.xl);
    const uint32_t wbh = bW;                   // hi half
    const uint32_t wbl = bW + 32768;           // lo half (byte offset)
    float accV[2][4][4], accG[2][4][4];

    auto combineFlush = [&](__nv_bfloat16* dst) {
        // obf aliases wbuf; prior sync guarantees weight reads done
        #pragma unroll
        for (int mt = 0; mt < 2; mt++) {
            int rA = m0w + mt * 16 + (lid >> 2);
            float mA = sm.mrow[rA], mB = sm.mrow[rA + 8];
            #pragma unroll
            for (int nt = 0; nt < 4; nt++) {
                int c = n0w + nt * 8 + 2 * (lid & 3);
                float v0 = accV[mt][nt][0] * mA * sigf(accG[mt][nt][0]);
                float v1 = accV[mt][nt][1] * mA * sigf(accG[mt][nt][1]);
                float v2 = accV[mt][nt][2] * mB * sigf(accG[mt][nt][2]);
                float v3 = accV[mt][nt][3] * mB * sigf(accG[mt][nt][3]);
                *(__nv_bfloat162*)&sm.obf[rA][c]     = __floats2bfloat162_rn(v0, v1);
                *(__nv_bfloat162*)&sm.obf[rA + 8][c] = __floats2bfloat162_rn(v2, v3);
            }
        }
        __syncthreads();
        #pragma unroll
        for (int t = 0; t < 32; t++) {         // transpose flush: [d][pos] planes
            int idx = tid + t * 256;
            int dch = idx >> 6, p = idx & 63;
            dst[(size_t)dch * NN + pos0 + p] = sm.obf[p][dch];
        }
        __syncthreads();
    };

    #pragma unroll 1
    for (int side = 0; side < 2; side++) {
        // value gemm (weight 2*side)
        gemm3(accV, m0w, n0w, lid, bxh, bxl, wbh, wbl);
        __syncthreads();                       // weight reads done
        cpW(2 * side + 1);                     // gate weight
        asm volatile("cp.async.wait_group 0;");
        __syncthreads();
        gemm3(accG, m0w, n0w, lid, bxh, bxl, wbh, wbl);
        __syncthreads();                       // weight reads done (obf aliases)
        combineFlush(side ? g_right : g_left);
        cpW(side ? 4 : 2);                     // next weight (Wr or Wog)
        asm volatile("cp.async.wait_group 0;");
        __syncthreads();
    }

    // ---- out_gate (Wog already resident) ----
    gemm3(accV, m0w, n0w, lid, bxh, bxl, wbh, wbl);
    #pragma unroll
    for (int mt = 0; mt < 2; mt++) {
        int rA = m0w + mt * 16 + (lid >> 2);
        #pragma unroll
        for (int nt = 0; nt < 4; nt++) {
            int c = n0w + nt * 8 + 2 * (lid & 3);
            float2 o0 = make_float2(sigf(accV[mt][nt][0]), sigf(accV[mt][nt][1]));
            float2 o1 = make_float2(sigf(accV[mt][nt][2]), sigf(accV[mt][nt][3]));
            *(float2*)(g_outgate + (size_t)(pos0 + rA) * 128 + c)     = o0;
            *(float2*)(g_outgate + (size_t)(pos0 + rA + 8) * 128 + c) = o1;
        }
    }
}

// =====================================================================
// Kernel B: per-channel batched GEMM — R10 HMMA cp.async (unchanged)
// =====================================================================
__device__ __forceinline__ uint32_t swOff(int row, int chunk) {
    return (uint32_t)(row * 64 + ((chunk ^ (row & 7)) << 3));
}

__global__ void __launch_bounds__(256) kernB()
{
    extern __shared__ __nv_bfloat16 smb[];
    const int tid = threadIdx.x;
    const int d  = blockIdx.z;
    const int i0 = blockIdx.y * 128;
    const int j0 = blockIdx.x * 128;
    const __nv_bfloat16* A = g_left  + (size_t)d * NN;
    const __nv_bfloat16* B = g_right + (size_t)d * NN;

    const int warp = tid >> 5, lane = tid & 31;
    const int m0 = (warp >> 2) * 64;
    const int n0 = (warp & 3) * 32;
    const uint32_t base = smem_u32(smb);

    float acc[4][4][4];
    #pragma unroll
    for (int mi = 0; mi < 4; mi++)
        #pragma unroll
        for (int ni = 0; ni < 4; ni++)
            #pragma unroll
            for (int e = 0; e < 4; e++) acc[mi][ni][e] = 0.f;

    const int aRow = ((lane & 8) ? 8 : 0) + (lane & 7);
    const int aChk = (lane >> 4);
    const int bRow = ((lane & 16) ? 8 : 0) + (lane & 7);
    const int bChk = ((lane >> 3) & 1);

    auto loadTile = [&](int st, int kb) {
        uint32_t sbase = base + (uint32_t)st * 32768;
        #pragma unroll
        for (int t = 0; t < 4; t++) {
            int idx = tid + t * 256;
            int r = idx >> 3, c = idx & 7;
            uint32_t so = swOff(r, c) * 2;
            cpa16(sbase + so,         A + (size_t)(i0 + r) * NDIM + kb + c * 8);
            cpa16(sbase + 16384 + so, B + (size_t)(j0 + r) * NDIM + kb + c * 8);
        }
        cpaCommit();
    };

    loadTile(0, 0);
    #pragma unroll 1
    for (int k = 0; k < 6; k++) {
        const int cur = k & 1;
        if (k < 5) loadTile(1 - cur, (k + 1) * 64);
        if (k < 5) asm volatile("cp.async.wait_group 1;");
        else       asm volatile("cp.async.wait_group 0;");
        __syncthreads();

        const uint32_t sA = base + (uint32_t)cur * 32768;
        const uint32_t sB = sA + 16384;
        #pragma unroll
        for (int kk = 0; kk < 64; kk += 16) {
            uint32_t af[4][4];
            #pragma unroll
            for (int mi = 0; mi < 4; mi++) {
                int row = m0 + mi * 16 + aRow;
                ldm4(af[mi], sA + swOff(row, (kk >> 3) + aChk) * 2);
            }
            uint32_t bf[2][4];
            #pragma unroll
            for (int p = 0; p < 2; p++) {
                int row = n0 + p * 16 + bRow;
                ldm4(bf[p], sB + swOff(row, (kk >> 3) + bChk) * 2);
            }
            #pragma unroll
            for (int mi = 0; mi < 4; mi++) {
                mma16816(acc[mi][0], af[mi], bf[0][0], bf[0][1]);
                mma16816(acc[mi][1], af[mi], bf[0][2], bf[0][3]);
                mma16816(acc[mi][2], af[mi], bf[1][0], bf[1][1]);
                mma16816(acc[mi][3], af[mi], bf[1][2], bf[1][3]);
            }
        }
        __syncthreads();
    }

    __nv_bfloat16* C = g_accbf + (size_t)d * NN;
    const int r = lane >> 2, cp = (lane & 3) * 2;
    #pragma unroll
    for (int mi = 0; mi < 4; mi++)
        #pragma unroll
        for (int ni = 0; ni < 4; ni++) {
            int gi = i0 + m0 + mi * 16 + r;
            int gj = j0 + n0 + ni * 8 + cp;
            *(__nv_bfloat162*)(C + (size_t)gi * NDIM + gj) =
                __floats2bfloat162_rn(acc[mi][ni][0], acc[mi][ni][1]);
            *(__nv_bfloat162*)(C + (size_t)(gi + 8) * NDIM + gj) =
                __floats2bfloat162_rn(acc[mi][ni][2], acc[mi][ni][3]);
        }
}

// =====================================================================
// Kernel C v4: out-LN + out_gate + @W_out^T — pre-split W_out,
// split-phase cp.async weight copy overlapping gather/LN
// =====================================================================
struct SmemC3 {
    __nv_bfloat16 xh[64 * 128];     // 16 KB  activation hi frags
    __nv_bfloat16 xl[64 * 128];     // 16 KB  activation lo frags
    __nv_bfloat16 wh[128 * 128];    // 32 KB  W_out hi frags
    __nv_bfloat16 wl[128 * 128];    // 32 KB  W_out lo frags; first 18.4KB doubles
                                    //        as bf16 gather stage [dch][72]
    float onw[128];
    float onb[128];
};  // ~97 KB -> 2 CTAs/SM

__global__ void __launch_bounds__(256, 2)
kernC(const float* __restrict__ onw, const float* __restrict__ onb,
      float* __restrict__ out)
{
    extern __shared__ char raw[];
    SmemC3& sm = *reinterpret_cast<SmemC3*>(raw);
    const int tid = threadIdx.x;
    const int pos0 = blockIdx.x * 64;
    const int wid = tid >> 5, lid = tid & 31;

    // g0: coalesced gather of the 64x128 bf16 tile into wl-stage [dch][72]
    const uint32_t bstage = smem_u32(sm.wl);
    #pragma unroll
    for (int t = 0; t < 4; t++) {
        int u = tid + t * 256;
        int dch = u >> 3, p0 = (u & 7) * 8;
        cpa16(bstage + (uint32_t)(dch * 72 + p0) * 2,
              g_accbf + (size_t)dch * NN + pos0 + p0);
    }
    cpaCommit();

    // g1: W_out hi half copy (wh is untouched by gather/LN — full overlap)
    const uint32_t bwh = smem_u32(sm.wh);
    {
        const __nv_bfloat16* src = g_wsp + 5 * (size_t)32768;
        #pragma unroll
        for (int t = 0; t < 8; t++) {
            int c = tid + t * 256;            // 2048 chunks of 16B
            cpa16(bwh + c * 16, src + c * 8);
        }
        cpaCommit();
    }

    if (tid < 128) { sm.onw[tid] = onw[tid]; sm.onb[tid] = onb[tid]; }
    asm volatile("cp.async.wait_group 1;");   // g0 (gather) done; g1 may fly
    __syncthreads();

    // out-LN + gate + hi/lo split (warp wid -> rows wid*8..+7)
    #pragma unroll
    for (int rr = 0; rr < 8; rr++) {
        int p = wid * 8 + rr;
        float v[4];
        #pragma unroll
        for (int t = 0; t < 4; t++) {
            int dch = lid + 32 * t;
            v[t] = __bfloat162float(sm.wl[dch * 72 + p]);
        }
        float ssum = v[0] + v[1] + v[2] + v[3];
        float q = v[0]*v[0] + v[1]*v[1] + v[2]*v[2] + v[3]*v[3];
        #pragma unroll
        for (int o = 16; o; o >>= 1) {
            ssum += __shfl_xor_sync(0xffffffffu, ssum, o);
            q    += __shfl_xor_sync(0xffffffffu, q, o);
        }
        float mu = ssum * (1.f / 128.f);
        float rstd = rsqrtf(q * (1.f / 128.f) - mu * mu + 1e-5f);
        const float* og = g_outgate + (size_t)(pos0 + p) * 128;
        #pragma unroll
        for (int t = 0; t < 4; t++) {
            int h = lid + 32 * t;
            float y = ((v[t] - mu) * rstd * sm.onw[h] + sm.onb[h]) * og[h];
            __nv_bfloat16 hi = __float2bfloat16(y);
            __nv_bfloat16 lo = __float2bfloat16(y - __bfloat162float(hi));
            uint32_t off = sw128(p, h >> 3) + (h & 7);
            sm.xh[off] = hi;
            sm.xl[off] = lo;
        }
    }
    __syncthreads();                 // all stage (wl) reads done before overwrite

    // g2: W_out lo half copy into wl (overwrites stage)
    const uint32_t bwl = smem_u32(sm.wl);
    {
        const __nv_bfloat16* src = g_wsp + 5 * (size_t)32768 + 16384;
        #pragma unroll
        for (int t = 0; t < 8; t++) {
            int c = tid + t * 256;
            cpa16(bwl + c * 16, src + c * 8);
        }
        cpaCommit();
    }
    asm volatile("cp.async.wait_group 0;");   // g1 + g2 done
    __syncthreads();

    const int m0w = (wid >> 2) * 32;
    const int n0w = (wid & 3) * 32;
    const uint32_t bxh = smem_u32(sm.xh);
    const uint32_t bxl = smem_u32(sm.xl);
    float acc[2][4][4];
    gemm3(acc, m0w, n0w, lid, bxh, bxl, bwh, bwl);

    #pragma unroll
    for (int mt = 0; mt < 2; mt++) {
        int rA = m0w + mt * 16 + (lid >> 2);
        #pragma unroll
        for (int nt = 0; nt < 4; nt++) {
            int c = n0w + nt * 8 + 2 * (lid & 3);
            *(float2*)(out + (size_t)(pos0 + rA) * 128 + c) =
                make_float2(acc[mt][nt][0], acc[mt][nt][1]);
            *(float2*)(out + (size_t)(pos0 + rA + 8) * 128 + c) =
                make_float2(acc[mt][nt][2], acc[mt][nt][3]);
        }
    }
}

// =====================================================================
extern "C" void kernel_launch(void* const* d_in, const int* in_sizes, int n_in,
                              void* d_out, int out_size)
{
    (void)in_sizes; (void)n_in; (void)out_size;
    const float* x    = (const float*)d_in[0];
    const float* mask = (const float*)d_in[1];
    const float* nw   = (const float*)d_in[2];
    const float* nb   = (const float*)d_in[3];
    const float* Wl   = (const float*)d_in[4];
    const float* Wr   = (const float*)d_in[5];
    const float* Wlg  = (const float*)d_in[6];
    const float* Wrg  = (const float*)d_in[7];
    const float* Wog  = (const float*)d_in[8];
    const float* onw  = (const float*)d_in[9];
    const float* onb  = (const float*)d_in[10];
    const float* Wout = (const float*)d_in[11];
    float* out = (float*)d_out;

    cudaFuncSetAttribute(kernA, cudaFuncAttributeMaxDynamicSharedMemorySize, (int)sizeof(SmemA6));
    cudaFuncSetAttribute(kernB, cudaFuncAttributeMaxDynamicSharedMemorySize, 65536);
    cudaFuncSetAttribute(kernC, cudaFuncAttributeMaxDynamicSharedMemorySize, (int)sizeof(SmemC3));

    kernW<<<6, 256>>>(Wl, Wlg, Wr, Wrg, Wog, Wout);
    kernA<<<NN / 64, 256, sizeof(SmemA6)>>>(x, mask, nw, nb);
    kernB<<<dim3(3, 3, 128), 256, 65536>>>();
    kernC<<<NN / 64, 256, sizeof(SmemC3)>>>(onw, onb, out);
}

// round 17
// speedup vs baseline: 1.1621x; 1.0412x over previous
#include <cuda_runtime.h>
#include <cuda_bf16.h>
#include <cstdint>

#define NDIM 384
#define NN   (NDIM * NDIM)   // 147456
#define DDIM 128

// ---- scratch (device globals; no allocation allowed) ----
__device__ __nv_bfloat16 g_left [(size_t)DDIM * NN];   // [d][i*N+k] bf16
__device__ __nv_bfloat16 g_right[(size_t)DDIM * NN];   // [d][j*N+k] bf16
__device__ float         g_outgate[(size_t)NN * DDIM]; // [pos][h] fp32
__device__ __nv_bfloat16 g_accbf[(size_t)DDIM * NN];   // [d][i*N+j] bf16 (einsum out)
__device__ __nv_bfloat16 g_wsp[6 * 32768];             // pre-split weights, frag layout
                                                       // [w]: 0..4 proj, 5=Wout

__device__ __forceinline__ float sigf(float v) { return 1.f / (1.f + __expf(-v)); }

// ---- shared mma helpers ----
__device__ __forceinline__ void ldm4(uint32_t (&r)[4], uint32_t saddr) {
    asm volatile("ldmatrix.sync.aligned.m8n8.x4.shared.b16 {%0,%1,%2,%3}, [%4];"
        : "=r"(r[0]), "=r"(r[1]), "=r"(r[2]), "=r"(r[3]) : "r"(saddr));
}
__device__ __forceinline__ void mma16816(float (&d)[4], const uint32_t (&a)[4],
                                         uint32_t b0, uint32_t b1) {
    asm volatile("mma.sync.aligned.m16n8k16.row.col.f32.bf16.bf16.f32 "
        "{%0,%1,%2,%3}, {%4,%5,%6,%7}, {%8,%9}, {%0,%1,%2,%3};"
        : "+f"(d[0]), "+f"(d[1]), "+f"(d[2]), "+f"(d[3])
        : "r"(a[0]), "r"(a[1]), "r"(a[2]), "r"(a[3]), "r"(b0), "r"(b1));
}
__device__ __forceinline__ void cpa16(uint32_t dst, const void* src) {
    asm volatile("cp.async.cg.shared.global [%0], [%1], 16;" :: "r"(dst), "l"(src));
}
__device__ __forceinline__ void cpaCommit() { asm volatile("cp.async.commit_group;"); }

__device__ __forceinline__ uint32_t smem_u32(const void* p) {
    return (uint32_t)__cvta_generic_to_shared(p);
}

// 128-col swizzled offset (elements)
__device__ __forceinline__ uint32_t sw128(int row, int chunk) {
    return (uint32_t)(row * 128 + (((chunk & 7) ^ (row & 7)) << 3) + ((chunk & 8) << 3));
}

// 3-pass split gemm (bf16x3): one accumulator, 32x32 warp tile, K=128
__device__ __forceinline__ void gemm3(float acc[2][4][4], int m0w, int n0w, int lane,
                                      uint32_t bxh, uint32_t bxl,
                                      uint32_t bwh, uint32_t bwl) {
    #pragma unroll
    for (int mi = 0; mi < 2; mi++)
        #pragma unroll
        for (int ni = 0; ni < 4; ni++)
            #pragma unroll
            for (int e = 0; e < 4; e++) acc[mi][ni][e] = 0.f;

    const int aRow = ((lane & 8) ? 8 : 0) + (lane & 7);
    const int aChk = (lane >> 4);
    const int bRow = ((lane & 16) ? 8 : 0) + (lane & 7);
    const int bChk = (lane >> 3) & 1;

    #pragma unroll
    for (int ks = 0; ks < 8; ks++) {
        uint32_t ah[2][4], al[2][4], bh[2][4], bl[2][4];
        #pragma unroll
        for (int mi = 0; mi < 2; mi++) {
            uint32_t off = sw128(m0w + mi * 16 + aRow, ks * 2 + aChk) * 2;
            ldm4(ah[mi], bxh + off);
            ldm4(al[mi], bxl + off);
        }
        #pragma unroll
        for (int p = 0; p < 2; p++) {
            uint32_t off = sw128(n0w + p * 16 + bRow, ks * 2 + bChk) * 2;
            ldm4(bh[p], bwh + off);
            ldm4(bl[p], bwl + off);
        }
        #pragma unroll
        for (int mi = 0; mi < 2; mi++) {
            mma16816(acc[mi][0], ah[mi], bh[0][0], bh[0][1]);
            mma16816(acc[mi][1], ah[mi], bh[0][2], bh[0][3]);
            mma16816(acc[mi][2], ah[mi], bh[1][0], bh[1][1]);
            mma16816(acc[mi][3], ah[mi], bh[1][2], bh[1][3]);
            mma16816(acc[mi][0], ah[mi], bl[0][0], bl[0][1]);
            mma16816(acc[mi][1], ah[mi], bl[0][2], bl[0][3]);
            mma16816(acc[mi][2], ah[mi], bl[1][0], bl[1][1]);
            mma16816(acc[mi][3], ah[mi], bl[1][2], bl[1][3]);
            mma16816(acc[mi][0], al[mi], bh[0][0], bh[0][1]);
            mma16816(acc[mi][1], al[mi], bh[0][2], bh[0][3]);
            mma16816(acc[mi][2], al[mi], bh[1][0], bh[1][1]);
            mma16816(acc[mi][3], al[mi], bh[1][2], bh[1][3]);
        }
    }
}

// =====================================================================
// Kernel W: pre-split all 6 weights into bf16 hi/lo frag layout
// =====================================================================
__global__ void __launch_bounds__(256) kernW(
    const float* __restrict__ Wl, const float* __restrict__ Wlg,
    const float* __restrict__ Wr, const float* __restrict__ Wrg,
    const float* __restrict__ Wog, const float* __restrict__ Wout)
{
    const float* W = (blockIdx.x == 0) ? Wl : (blockIdx.x == 1) ? Wlg :
                     (blockIdx.x == 2) ? Wr : (blockIdx.x == 3) ? Wrg :
                     (blockIdx.x == 4) ? Wog : Wout;
    __nv_bfloat16* dh = g_wsp + (size_t)blockIdx.x * 32768;
    __nv_bfloat16* dl = dh + 16384;
    const int tid = threadIdx.x;
    #pragma unroll
    for (int t = 0; t < 16; t++) {
        int idx = tid + t * 256;
        int h = idx >> 5, kq = idx & 31;
        float4 w = *(const float4*)(W + h * 128 + kq * 4);
        __nv_bfloat162 h01 = __floats2bfloat162_rn(w.x, w.y);
        __nv_bfloat162 h23 = __floats2bfloat162_rn(w.z, w.w);
        __nv_bfloat162 l01 = __floats2bfloat162_rn(w.x - __bfloat162float(h01.x),
                                                   w.y - __bfloat162float(h01.y));
        __nv_bfloat162 l23 = __floats2bfloat162_rn(w.z - __bfloat162float(h23.x),
                                                   w.w - __bfloat162float(h23.y));
        uint32_t off = sw128(h, kq >> 1) + ((kq & 1) << 2);
        *(__nv_bfloat162*)(dh + off)     = h01;
        *(__nv_bfloat162*)(dh + off + 2) = h23;
        *(__nv_bfloat162*)(dl + off)     = l01;
        *(__nv_bfloat162*)(dl + off + 2) = l23;
    }
}

// =====================================================================
// Kernel A v6: LN + 5 projections + gating — 64 rows, 256 thr,
// pre-split weights, single weight buffer (obf aliased), 2 CTAs/SM
// =====================================================================
struct SmemA6 {
    __nv_bfloat16 xh[64 * 128];          // 16 KB
    __nv_bfloat16 xl[64 * 128];          // 16 KB
    union {
        __nv_bfloat16 wbuf[32768];       // 64 KB: hi [0,16384) lo [16384,32768)
        __nv_bfloat16 obf[64][130];      // 16.6 KB (aliases wbuf)
    };
    float mrow[64];
    float nw[128];
    float nb[128];
};  // ~97.4 KB -> 2 CTAs/SM

__global__ void __launch_bounds__(256, 2)
kernA(const float* __restrict__ x, const float* __restrict__ mask,
      const float* __restrict__ nw, const float* __restrict__ nb)
{
    extern __shared__ char raw[];
    SmemA6& sm = *reinterpret_cast<SmemA6*>(raw);
    const int tid = threadIdx.x;
    const int pos0 = blockIdx.x * 64;
    const int wid = tid >> 5, lid = tid & 31;

    const uint32_t bW = smem_u32(sm.wbuf);
    auto cpW = [&](int w) {                    // copy pre-split weight w into wbuf
        const __nv_bfloat16* src = g_wsp + (size_t)w * 32768;
        #pragma unroll
        for (int t = 0; t < 16; t++) {
            int c = tid + t * 256;             // 16B chunk, 4096 total
            cpa16(bW + c * 16, src + c * 8);
        }
        cpaCommit();
    };

    cpW(0);                                    // Wl in flight over LN

    if (tid < 128) { sm.nw[tid] = nw[tid]; sm.nb[tid] = nb[tid]; }
    if (tid < 64)  sm.mrow[tid] = mask[pos0 + tid];
    __syncthreads();

    // LayerNorm: 8 warps x 8 rows = 64 rows
    #pragma unroll
    for (int rr = 0; rr < 8; rr++) {
        int r = wid * 8 + rr;
        float4 v = *(const float4*)(x + (size_t)(pos0 + r) * 128 + lid * 4);
        float s = v.x + v.y + v.z + v.w;
        float q = v.x * v.x + v.y * v.y + v.z * v.z + v.w * v.w;
        #pragma unroll
        for (int o = 16; o; o >>= 1) {
            s += __shfl_xor_sync(0xffffffffu, s, o);
            q += __shfl_xor_sync(0xffffffffu, q, o);
        }
        float mu = s * (1.f / 128.f);
        float rstd = rsqrtf(q * (1.f / 128.f) - mu * mu + 1e-5f);
        float4 nwv = *(const float4*)&sm.nw[lid * 4];
        float4 nbv = *(const float4*)&sm.nb[lid * 4];
        float y0 = (v.x - mu) * rstd * nwv.x + nbv.x;
        float y1 = (v.y - mu) * rstd * nwv.y + nbv.y;
        float y2 = (v.z - mu) * rstd * nwv.z + nbv.z;
        float y3 = (v.w - mu) * rstd * nwv.w + nbv.w;
        __nv_bfloat162 h01 = __floats2bfloat162_rn(y0, y1);
        __nv_bfloat162 h23 = __floats2bfloat162_rn(y2, y3);
        __nv_bfloat162 l01 = __floats2bfloat162_rn(y0 - __bfloat162float(h01.x),
                                                   y1 - __bfloat162float(h01.y));
        __nv_bfloat162 l23 = __floats2bfloat162_rn(y2 - __bfloat162float(h23.x),
                                                   y3 - __bfloat162float(h23.y));
        uint32_t off = sw128(r, lid >> 1) + ((lid & 1) << 2);
        *(__nv_bfloat162*)(sm.xh + off)     = h01;
        *(__nv_bfloat162*)(sm.xh + off + 2) = h23;
        *(__nv_bfloat162*)(sm.xl + off)     = l01;
        *(__nv_bfloat162*)(sm.xl + off + 2) = l23;
    }
    asm volatile("cp.async.wait_group 0;");    // Wl resident
    __syncthreads();

    const int m0w = (wid >> 2) * 32;           // 0 or 32
    const int n0w = (wid & 3) * 32;            // 0..96
    const uint32_t bxh = smem_u32(sm.xh);
    const uint32_t bxl = smem_u32(sm.xl);
    const uint32_t wbh = bW;                   // hi half
    const uint32_t wbl = bW + 32768;           // lo half (byte offset)
    float accV[2][4][4], accG[2][4][4];

    auto combineFlush = [&](__nv_bfloat16* dst) {
        // obf aliases wbuf; prior sync guarantees weight reads done
        #pragma unroll
        for (int mt = 0; mt < 2; mt++) {
            int rA = m0w + mt * 16 + (lid >> 2);
            float mA = sm.mrow[rA], mB = sm.mrow[rA + 8];
            #pragma unroll
            for (int nt = 0; nt < 4; nt++) {
                int c = n0w + nt * 8 + 2 * (lid & 3);
                float v0 = accV[mt][nt][0] * mA * sigf(accG[mt][nt][0]);
                float v1 = accV[mt][nt][1] * mA * sigf(accG[mt][nt][1]);
                float v2 = accV[mt][nt][2] * mB * sigf(accG[mt][nt][2]);
                float v3 = accV[mt][nt][3] * mB * sigf(accG[mt][nt][3]);
                *(__nv_bfloat162*)&sm.obf[rA][c]     = __floats2bfloat162_rn(v0, v1);
                *(__nv_bfloat162*)&sm.obf[rA + 8][c] = __floats2bfloat162_rn(v2, v3);
            }
        }
        __syncthreads();
        #pragma unroll
        for (int t = 0; t < 32; t++) {         // transpose flush: [d][pos] planes
            int idx = tid + t * 256;
            int dch = idx >> 6, p = idx & 63;
            dst[(size_t)dch * NN + pos0 + p] = sm.obf[p][dch];
        }
        __syncthreads();
    };

    #pragma unroll 1
    for (int side = 0; side < 2; side++) {
        // value gemm (weight 2*side)
        gemm3(accV, m0w, n0w, lid, bxh, bxl, wbh, wbl);
        __syncthreads();                       // weight reads done
        cpW(2 * side + 1);                     // gate weight
        asm volatile("cp.async.wait_group 0;");
        __syncthreads();
        gemm3(accG, m0w, n0w, lid, bxh, bxl, wbh, wbl);
        __syncthreads();                       // weight reads done (obf aliases)
        combineFlush(side ? g_right : g_left);
        cpW(side ? 4 : 2);                     // next weight (Wr or Wog)
        asm volatile("cp.async.wait_group 0;");
        __syncthreads();
    }

    // ---- out_gate (Wog already resident) ----
    gemm3(accV, m0w, n0w, lid, bxh, bxl, wbh, wbl);
    #pragma unroll
    for (int mt = 0; mt < 2; mt++) {
        int rA = m0w + mt * 16 + (lid >> 2);
        #pragma unroll
        for (int nt = 0; nt < 4; nt++) {
            int c = n0w + nt * 8 + 2 * (lid & 3);
            float2 o0 = make_float2(sigf(accV[mt][nt][0]), sigf(accV[mt][nt][1]));
            float2 o1 = make_float2(sigf(accV[mt][nt][2]), sigf(accV[mt][nt][3]));
            *(float2*)(g_outgate + (size_t)(pos0 + rA) * 128 + c)     = o0;
            *(float2*)(g_outgate + (size_t)(pos0 + rA + 8) * 128 + c) = o1;
        }
    }
}

// =====================================================================
// Kernel B: per-channel batched GEMM — R10 HMMA cp.async (unchanged)
// =====================================================================
__device__ __forceinline__ uint32_t swOff(int row, int chunk) {
    return (uint32_t)(row * 64 + ((chunk ^ (row & 7)) << 3));
}

__global__ void __launch_bounds__(256) kernB()
{
    extern __shared__ __nv_bfloat16 smb[];
    const int tid = threadIdx.x;
    const int d  = blockIdx.z;
    const int i0 = blockIdx.y * 128;
    const int j0 = blockIdx.x * 128;
    const __nv_bfloat16* A = g_left  + (size_t)d * NN;
    const __nv_bfloat16* B = g_right + (size_t)d * NN;

    const int warp = tid >> 5, lane = tid & 31;
    const int m0 = (warp >> 2) * 64;
    const int n0 = (warp & 3) * 32;
    const uint32_t base = smem_u32(smb);

    float acc[4][4][4];
    #pragma unroll
    for (int mi = 0; mi < 4; mi++)
        #pragma unroll
        for (int ni = 0; ni < 4; ni++)
            #pragma unroll
            for (int e = 0; e < 4; e++) acc[mi][ni][e] = 0.f;

    const int aRow = ((lane & 8) ? 8 : 0) + (lane & 7);
    const int aChk = (lane >> 4);
    const int bRow = ((lane & 16) ? 8 : 0) + (lane & 7);
    const int bChk = ((lane >> 3) & 1);

    auto loadTile = [&](int st, int kb) {
        uint32_t sbase = base + (uint32_t)st * 32768;
        #pragma unroll
        for (int t = 0; t < 4; t++) {
            int idx = tid + t * 256;
            int r = idx >> 3, c = idx & 7;
            uint32_t so = swOff(r, c) * 2;
            cpa16(sbase + so,         A + (size_t)(i0 + r) * NDIM + kb + c * 8);
            cpa16(sbase + 16384 + so, B + (size_t)(j0 + r) * NDIM + kb + c * 8);
        }
        cpaCommit();
    };

    loadTile(0, 0);
    #pragma unroll 1
    for (int k = 0; k < 6; k++) {
        const int cur = k & 1;
        if (k < 5) loadTile(1 - cur, (k + 1) * 64);
        if (k < 5) asm volatile("cp.async.wait_group 1;");
        else       asm volatile("cp.async.wait_group 0;");
        __syncthreads();

        const uint32_t sA = base + (uint32_t)cur * 32768;
        const uint32_t sB = sA + 16384;
        #pragma unroll
        for (int kk = 0; kk < 64; kk += 16) {
            uint32_t af[4][4];
            #pragma unroll
            for (int mi = 0; mi < 4; mi++) {
                int row = m0 + mi * 16 + aRow;
                ldm4(af[mi], sA + swOff(row, (kk >> 3) + aChk) * 2);
            }
            uint32_t bf[2][4];
            #pragma unroll
            for (int p = 0; p < 2; p++) {
                int row = n0 + p * 16 + bRow;
                ldm4(bf[p], sB + swOff(row, (kk >> 3) + bChk) * 2);
            }
            #pragma unroll
            for (int mi = 0; mi < 4; mi++) {
                mma16816(acc[mi][0], af[mi], bf[0][0], bf[0][1]);
                mma16816(acc[mi][1], af[mi], bf[0][2], bf[0][3]);
                mma16816(acc[mi][2], af[mi], bf[1][0], bf[1][1]);
                mma16816(acc[mi][3], af[mi], bf[1][2], bf[1][3]);
            }
        }
        __syncthreads();
    }

    __nv_bfloat16* C = g_accbf + (size_t)d * NN;
    const int r = lane >> 2, cp = (lane & 3) * 2;
    #pragma unroll
    for (int mi = 0; mi < 4; mi++)
        #pragma unroll
        for (int ni = 0; ni < 4; ni++) {
            int gi = i0 + m0 + mi * 16 + r;
            int gj = j0 + n0 + ni * 8 + cp;
            *(__nv_bfloat162*)(C + (size_t)gi * NDIM + gj) =
                __floats2bfloat162_rn(acc[mi][ni][0], acc[mi][ni][1]);
            *(__nv_bfloat162*)(C + (size_t)(gi + 8) * NDIM + gj) =
                __floats2bfloat162_rn(acc[mi][ni][2], acc[mi][ni][3]);
        }
}

// =====================================================================
// Kernel C v4: out-LN + out_gate + @W_out^T — pre-split W_out,
// split-phase cp.async weight copy overlapping gather/LN
// =====================================================================
struct SmemC3 {
    __nv_bfloat16 xh[64 * 128];     // 16 KB  activation hi frags
    __nv_bfloat16 xl[64 * 128];     // 16 KB  activation lo frags
    __nv_bfloat16 wh[128 * 128];    // 32 KB  W_out hi frags
    __nv_bfloat16 wl[128 * 128];    // 32 KB  W_out lo frags; first 18.4KB doubles
                                    //        as bf16 gather stage [dch][72]
    float onw[128];
    float onb[128];
};  // ~97 KB -> 2 CTAs/SM

__global__ void __launch_bounds__(256, 2)
kernC(const float* __restrict__ onw, const float* __restrict__ onb,
      float* __restrict__ out)
{
    extern __shared__ char raw[];
    SmemC3& sm = *reinterpret_cast<SmemC3*>(raw);
    const int tid = threadIdx.x;
    const int pos0 = blockIdx.x * 64;
    const int wid = tid >> 5, lid = tid & 31;

    // g0: coalesced gather of the 64x128 bf16 tile into wl-stage [dch][72]
    const uint32_t bstage = smem_u32(sm.wl);
    #pragma unroll
    for (int t = 0; t < 4; t++) {
        int u = tid + t * 256;
        int dch = u >> 3, p0 = (u & 7) * 8;
        cpa16(bstage + (uint32_t)(dch * 72 + p0) * 2,
              g_accbf + (size_t)dch * NN + pos0 + p0);
    }
    cpaCommit();

    // g1: W_out hi half copy (wh is untouched by gather/LN — full overlap)
    const uint32_t bwh = smem_u32(sm.wh);
    {
        const __nv_bfloat16* src = g_wsp + 5 * (size_t)32768;
        #pragma unroll
        for (int t = 0; t < 8; t++) {
            int c = tid + t * 256;            // 2048 chunks of 16B
            cpa16(bwh + c * 16, src + c * 8);
        }
        cpaCommit();
    }

    if (tid < 128) { sm.onw[tid] = onw[tid]; sm.onb[tid] = onb[tid]; }
    asm volatile("cp.async.wait_group 1;");   // g0 (gather) done; g1 may fly
    __syncthreads();

    // out-LN + gate + hi/lo split (warp wid -> rows wid*8..+7)
    #pragma unroll
    for (int rr = 0; rr < 8; rr++) {
        int p = wid * 8 + rr;
        float v[4];
        #pragma unroll
        for (int t = 0; t < 4; t++) {
            int dch = lid + 32 * t;
            v[t] = __bfloat162float(sm.wl[dch * 72 + p]);
        }
        float ssum = v[0] + v[1] + v[2] + v[3];
        float q = v[0]*v[0] + v[1]*v[1] + v[2]*v[2] + v[3]*v[3];
        #pragma unroll
        for (int o = 16; o; o >>= 1) {
            ssum += __shfl_xor_sync(0xffffffffu, ssum, o);
            q    += __shfl_xor_sync(0xffffffffu, q, o);
        }
        float mu = ssum * (1.f / 128.f);
        float rstd = rsqrtf(q * (1.f / 128.f) - mu * mu + 1e-5f);
        const float* og = g_outgate + (size_t)(pos0 + p) * 128;
        #pragma unroll
        for (int t = 0; t < 4; t++) {
            int h = lid + 32 * t;
            float y = ((v[t] - mu) * rstd * sm.onw[h] + sm.onb[h]) * og[h];
            __nv_bfloat16 hi = __float2bfloat16(y);
            __nv_bfloat16 lo = __float2bfloat16(y - __bfloat162float(hi));
            uint32_t off = sw128(p, h >> 3) + (h & 7);
            sm.xh[off] = hi;
            sm.xl[off] = lo;
        }
    }
    __syncthreads();                 // all stage (wl) reads done before overwrite

    // g2: W_out lo half copy into wl (overwrites stage)
    const uint32_t bwl = smem_u32(sm.wl);
    {
        const __nv_bfloat16* src = g_wsp + 5 * (size_t)32768 + 16384;
        #pragma unroll
        for (int t = 0; t < 8; t++) {
            int c = tid + t * 256;
            cpa16(bwl + c * 16, src + c * 8);
        }
        cpaCommit();
    }
    asm volatile("cp.async.wait_group 0;");   // g1 + g2 done
    __syncthreads();

    const int m0w = (wid >> 2) * 32;
    const int n0w = (wid & 3) * 32;
    const uint32_t bxh = smem_u32(sm.xh);
    const uint32_t bxl = smem_u32(sm.xl);
    float acc[2][4][4];
    gemm3(acc, m0w, n0w, lid, bxh, bxl, bwh, bwl);

    #pragma unroll
    for (int mt = 0; mt < 2; mt++) {
        int rA = m0w + mt * 16 + (lid >> 2);
        #pragma unroll
        for (int nt = 0; nt < 4; nt++) {
            int c = n0w + nt * 8 + 2 * (lid & 3);
            *(float2*)(out + (size_t)(pos0 + rA) * 128 + c) =
                make_float2(acc[mt][nt][0], acc[mt][nt][1]);
            *(float2*)(out + (size_t)(pos0 + rA + 8) * 128 + c) =
                make_float2(acc[mt][nt][2], acc[mt][nt][3]);
        }
    }
}

// =====================================================================
extern "C" void kernel_launch(void* const* d_in, const int* in_sizes, int n_in,
                              void* d_out, int out_size)
{
    (void)in_sizes; (void)n_in; (void)out_size;
    const float* x    = (const float*)d_in[0];
    const float* mask = (const float*)d_in[1];
    const float* nw   = (const float*)d_in[2];
    const float* nb   = (const float*)d_in[3];
    const float* Wl   = (const float*)d_in[4];
    const float* Wr   = (const float*)d_in[5];
    const float* Wlg  = (const float*)d_in[6];
    const float* Wrg  = (const float*)d_in[7];
    const float* Wog  = (const float*)d_in[8];
    const float* onw  = (const float*)d_in[9];
    const float* onb  = (const float*)d_in[10];
    const float* Wout = (const float*)d_in[11];
    float* out = (float*)d_out;

    cudaFuncSetAttribute(kernA, cudaFuncAttributeMaxDynamicSharedMemorySize, (int)sizeof(SmemA6));
    cudaFuncSetAttribute(kernB, cudaFuncAttributeMaxDynamicSharedMemorySize, 65536);
    cudaFuncSetAttribute(kernC, cudaFuncAttributeMaxDynamicSharedMemorySize, (int)sizeof(SmemC3));

    kernW<<<6, 256>>>(Wl, Wlg, Wr, Wrg, Wog, Wout);
    kernA<<<NN / 64, 256, sizeof(SmemA6)>>>(x, mask, nw, nb);
    kernB<<<dim3(3, 3, 128), 256, 65536>>>();
    kernC<<<NN / 64, 256, sizeof(SmemC3)>>>(onw, onb, out);
}